// round 1
// baseline (speedup 1.0000x reference)
#include <cuda_runtime.h>
#include <cstdint>
#include <math.h>

// Problem dimensions (fixed by the dataset)
#define H   200
#define S   1025
#define W   128
#define MID 512
#define NSEQ_PREV 513   // sentences 0..512
#define K2  (2*H)       // 400 : [x ; h]

// ---------------------------------------------------------------------------
// Device scratch (static globals: no allocation anywhere)
// ---------------------------------------------------------------------------
// Gate-interleaved weights: g_W4[set][kappa*400 + k] is float4 = (i,f,g,o)
// weights of hidden index kappa at input k (k<200 -> wih, k>=200 -> whh).
__device__ float4 g_W4[4][H * K2];   // 4 sets x 200 x 400 float4 = 5.1 MB
__device__ float4 g_b4[4][H];        // combined bias bih+bhh, interleaved
__device__ int    g_order[S];        // sentence indices sorted by length desc
__device__ int    g_cnt[W];          // cnt[t] = #sentences with len > t
__device__ float  g_hA[S * H];       // phase-A hidden state (rank order)
__device__ float  g_cA[S * H];       // phase-A cell state   (rank order)
__device__ float  g_emb[S * H];      // sentence embeddings (original order)
__device__ float4 g_GT4[W * H];          // tgt input projection
__device__ float4 g_GP4[NSEQ_PREV * H];  // prev input projection
__device__ float4 g_GQ4[NSEQ_PREV * H];  // post input projection (reversed)
__device__ float  g_prevh[H];
__device__ float  g_posth[H];

__device__ __forceinline__ float sigf(float x) { return 1.0f / (1.0f + expf(-x)); }

// ---------------------------------------------------------------------------
// Kernel 1: counting sort of sentences by length (descending) + active counts
// ---------------------------------------------------------------------------
__global__ void sort_kernel(const int* __restrict__ lengths) {
    __shared__ int hist[W + 1];
    __shared__ int cur[W + 1];
    int tid = threadIdx.x;
    for (int i = tid; i <= W; i += blockDim.x) hist[i] = 0;
    __syncthreads();
    for (int s = tid; s < S; s += blockDim.x) atomicAdd(&hist[lengths[s]], 1);
    __syncthreads();
    if (tid == 0) {
        int run = 0;
        for (int L = W; L >= 1; L--) { cur[L] = run; run += hist[L]; }
        // cnt[t] = #{len > t}; all len >= 1 so cnt[0] = S
        for (int t = 0; t < W; t++) g_cnt[t] = (t == 0) ? run : cur[t];
    }
    __syncthreads();
    for (int s = tid; s < S; s += blockDim.x) {
        int r = atomicAdd(&cur[lengths[s]], 1);
        g_order[r] = s;   // rank within equal lengths is nondeterministic but
                          // results are permutation-invariant -> bitwise stable
    }
}

// ---------------------------------------------------------------------------
// Kernel 2: reorder weights into gate-interleaved float4 layout + fused bias
// ---------------------------------------------------------------------------
__global__ void prep_kernel(const float* __restrict__ wih,
                            const float* __restrict__ whh,
                            const float* __restrict__ bih,
                            const float* __restrict__ bhh, int set) {
    int idx = blockIdx.x * blockDim.x + threadIdx.x;
    if (idx >= H * K2) return;
    int kap = idx / K2;
    int k   = idx % K2;
    float4 v;
    if (k < H) {
        v.x = wih[(0 * H + kap) * H + k];
        v.y = wih[(1 * H + kap) * H + k];
        v.z = wih[(2 * H + kap) * H + k];
        v.w = wih[(3 * H + kap) * H + k];
    } else {
        int kk = k - H;
        v.x = whh[(0 * H + kap) * H + kk];
        v.y = whh[(1 * H + kap) * H + kk];
        v.z = whh[(2 * H + kap) * H + kk];
        v.w = whh[(3 * H + kap) * H + kk];
    }
    g_W4[set][idx] = v;
    if (k == 0) {
        float4 b;
        b.x = bih[0 * H + kap] + bhh[0 * H + kap];
        b.y = bih[1 * H + kap] + bhh[1 * H + kap];
        b.z = bih[2 * H + kap] + bhh[2 * H + kap];
        b.w = bih[3 * H + kap] + bhh[3 * H + kap];
        g_b4[set][kap] = b;
    }
}

// ---------------------------------------------------------------------------
// Kernel 3: init phase-A state in sorted-rank order
// ---------------------------------------------------------------------------
__global__ void init_kernel(const float* __restrict__ h0w,
                            const float* __restrict__ c0w) {
    int idx = blockIdx.x * blockDim.x + threadIdx.x;
    if (idx >= S * H) return;
    int r = idx / H, k = idx % H;
    int s = g_order[r];
    g_hA[idx] = h0w[s * H + k];
    g_cA[idx] = c0w[s * H + k];
}

// ---------------------------------------------------------------------------
// Kernel 4: one LSTM time step for all active sentences (fused GEMM + update)
//   Tile: 16 rows x 20 hidden-indices (= 80 gate outputs), 320 threads,
//   each thread computes all 4 gates of one (row, kappa) -> fused update.
// ---------------------------------------------------------------------------
#define MT 16
#define KT 20
__global__ __launch_bounds__(320) void step_kernel(const float* __restrict__ words,
                                                   const int* __restrict__ lengths,
                                                   int t) {
    int cnt = g_cnt[t];
    int mbase = blockIdx.y * MT;
    if (mbase >= cnt) return;

    __shared__ float Asm[MT][K2 + 1];   // [16][401], +1 pad kills bank conflicts
    int tid = threadIdx.x;

    // Stage A tile: rows = [x_t ; h] for 16 sentences (clamped for tail tiles)
    for (int idx = tid; idx < MT * K2; idx += 320) {
        int m = idx / K2, k = idx % K2;
        int r = mbase + m; if (r > S - 1) r = S - 1;
        float v;
        if (k < H) {
            int s = g_order[r];
            v = words[((long)s * W + t) * H + k];
        } else {
            v = g_hA[r * H + (k - H)];
        }
        Asm[m][k] = v;
    }
    __syncthreads();

    int m   = tid & 15;
    int kl  = tid >> 4;
    int kap = blockIdx.x * KT + kl;

    const float4* __restrict__ wr = &g_W4[0][kap * K2];
    float4 acc = g_b4[0][kap];
    const float* arow = Asm[m];
#pragma unroll 8
    for (int k = 0; k < K2; k++) {
        float a = arow[k];
        float4 w = wr[k];
        acc.x = fmaf(w.x, a, acc.x);
        acc.y = fmaf(w.y, a, acc.y);
        acc.z = fmaf(w.z, a, acc.z);
        acc.w = fmaf(w.w, a, acc.w);
    }

    int r = mbase + m;
    if (r < cnt) {
        float ig = sigf(acc.x);
        float fg = sigf(acc.y);
        float gg = tanhf(acc.z);
        float og = sigf(acc.w);
        int off = r * H + kap;
        float c = fg * g_cA[off] + ig * gg;
        float h = og * tanhf(c);
        g_cA[off] = c;
        g_hA[off] = h;
        int s = g_order[r];
        if (lengths[s] == t + 1) g_emb[s * H + kap] = h;
    }
}

// ---------------------------------------------------------------------------
// Kernel 5: input projections  out4[t][kap] = b4 + W_in . x(t)
//   x_sel: 0 = words[MID] -> g_GT4 ; 1 = emb forward -> g_GP4 ;
//          2 = emb reversed -> g_GQ4
// ---------------------------------------------------------------------------
__global__ void proj_kernel(const float* __restrict__ words, int x_sel, int T, int set) {
    int t = blockIdx.x;
    if (t >= T) return;
    const float* xbase;
    long xstride;
    float4* out;
    if (x_sel == 0)      { xbase = words + (long)MID * W * H; xstride =  H; out = g_GT4; }
    else if (x_sel == 1) { xbase = g_emb;                     xstride =  H; out = g_GP4; }
    else                 { xbase = g_emb + (long)(S - 1) * H; xstride = -H; out = g_GQ4; }

    __shared__ float xs[H];
    int tid = threadIdx.x;
    if (tid < H) xs[tid] = xbase[(long)t * xstride + tid];
    __syncthreads();
    if (tid >= H) return;
    int kap = tid;
    const float4* __restrict__ wr = &g_W4[set][kap * K2];
    float4 acc = g_b4[set][kap];
#pragma unroll 4
    for (int k = 0; k < H; k++) {
        float a = xs[k];
        float4 w = wr[k];
        acc.x = fmaf(w.x, a, acc.x);
        acc.y = fmaf(w.y, a, acc.y);
        acc.z = fmaf(w.z, a, acc.z);
        acc.w = fmaf(w.w, a, acc.w);
    }
    out[t * H + kap] = acc;
}

// ---------------------------------------------------------------------------
// Kernel 6: serial LSTM recurrence, 4-CTA cluster, whh slice resident in SMEM.
//   CTA r owns hidden indices [r*50, r*50+50) (all 4 gates, interleaved),
//   so the LSTM update is CTA-local; only h is broadcast via DSMEM per step.
// ---------------------------------------------------------------------------
#define CL 4
struct RecParams {
    int gx_sel;            // 0 g_GT4, 1 g_GP4, 2 g_GQ4
    int set;               // weight set index
    const float* h0;
    const float* c0;
    int out_sel;           // 0 -> g_emb[MID], 1 -> g_prevh, 2 -> g_posth
    int steps;             // fixed step count (if steps_dev == nullptr)
    const int* steps_dev;  // device override (tgt: &lengths[MID])
};

// Wsm: [50][200] float4 = 160000 B ; h_sm 256 f ; c_sm 64 f ; psum 200 float4
#define REC_SMEM (50 * H * 16 + 256 * 4 + 64 * 4 + 4 * 50 * 16)

__device__ __forceinline__ void cluster_sync_() {
    asm volatile("barrier.cluster.arrive.aligned;" ::: "memory");
    asm volatile("barrier.cluster.wait.aligned;" ::: "memory");
}

__global__ void __cluster_dims__(CL, 1, 1) __launch_bounds__(256, 1)
rec_kernel(RecParams p0, RecParams p1, int ncl) {
    int cid = blockIdx.x / CL;
    if (cid >= ncl) return;               // whole cluster exits together
    RecParams P = (cid == 0) ? p0 : p1;

    const float4* gx = (P.gx_sel == 0) ? g_GT4 : (P.gx_sel == 1) ? g_GP4 : g_GQ4;
    float* out = (P.out_sel == 0) ? (g_emb + (long)MID * H)
               : (P.out_sel == 1) ? g_prevh : g_posth;
    const float4* w4 = g_W4[P.set];

    extern __shared__ float smem[];
    float4* Wsm = (float4*)smem;                       // [50][200]
    float*  h_sm = (float*)(Wsm + 50 * H);             // [200] (pad 256)
    float*  c_sm = h_sm + 256;                         // [50]  (pad 64)
    float4* psum = (float4*)(c_sm + 64);               // [4][50]

    int tid = threadIdx.x;
    int r = blockIdx.x % CL;                           // cluster cta rank

    // Stage recurrent weight slice (rows r*50..r*50+49, k in [H, 2H))
    for (int idx = tid; idx < 50 * H; idx += 256) {
        int kl = idx / H, k = idx % H;
        Wsm[kl * H + k] = w4[(r * 50 + kl) * K2 + H + k];
    }
    for (int k = tid; k < H; k += 256) h_sm[k] = P.h0[k];
    if (tid < 50) c_sm[tid] = P.c0[r * 50 + tid];
    int steps = P.steps_dev ? P.steps_dev[0] : P.steps;
    __syncthreads();
    cluster_sync_();   // all CTAs' h_sm init done before anyone writes into it

    for (int t = 0; t < steps; t++) {
        if (tid < 200) {
            int c4 = tid & 3, kl = tid >> 2;
            float4 acc = make_float4(0.f, 0.f, 0.f, 0.f);
            const float4* wrow = &Wsm[kl * H + c4 * 50];
            const float* hp = &h_sm[c4 * 50];
#pragma unroll 10
            for (int k = 0; k < 50; k++) {
                float a = hp[k];
                float4 w = wrow[k];
                acc.x = fmaf(w.x, a, acc.x);
                acc.y = fmaf(w.y, a, acc.y);
                acc.z = fmaf(w.z, a, acc.z);
                acc.w = fmaf(w.w, a, acc.w);
            }
            psum[c4 * 50 + kl] = acc;
        }
        __syncthreads();
        if (tid < 50) {
            float4 g = gx[t * H + r * 50 + tid];
            float4 a0 = psum[0 * 50 + tid], a1 = psum[1 * 50 + tid];
            float4 a2 = psum[2 * 50 + tid], a3 = psum[3 * 50 + tid];
            g.x += a0.x + a1.x + a2.x + a3.x;
            g.y += a0.y + a1.y + a2.y + a3.y;
            g.z += a0.z + a1.z + a2.z + a3.z;
            g.w += a0.w + a1.w + a2.w + a3.w;
            float ig = sigf(g.x), fg = sigf(g.y), gg = tanhf(g.z), og = sigf(g.w);
            float cn = fg * c_sm[tid] + ig * gg;
            c_sm[tid] = cn;
            float hn = og * tanhf(cn);
            int hidx = r * 50 + tid;
            uint32_t laddr = (uint32_t)__cvta_generic_to_shared(&h_sm[hidx]);
#pragma unroll
            for (int tr = 0; tr < CL; tr++) {
                uint32_t raddr;
                asm volatile("mapa.shared::cluster.u32 %0, %1, %2;"
                             : "=r"(raddr) : "r"(laddr), "r"(tr));
                asm volatile("st.shared::cluster.f32 [%0], %1;"
                             :: "r"(raddr), "f"(hn) : "memory");
            }
        }
        cluster_sync_();   // release remote h writes / acquire for next GEMV
    }

    if (tid < 50) out[r * 50 + tid] = h_sm[r * 50 + tid];
}

// ---------------------------------------------------------------------------
// Kernel 7: final FC   out[j] = fc_b[j] + [prev;post] . fc_w[j, :]
// ---------------------------------------------------------------------------
__global__ void fc_kernel(const float* __restrict__ fcw,
                          const float* __restrict__ fcb,
                          float* __restrict__ out) {
    __shared__ float feat[K2];
    int tid = threadIdx.x;
    if (tid < H) { feat[tid] = g_prevh[tid]; feat[H + tid] = g_posth[tid]; }
    __syncthreads();
    if (tid < H) {
        float acc = fcb[tid];
        const float* wr = &fcw[tid * K2];
#pragma unroll 4
        for (int k = 0; k < K2; k++) acc = fmaf(wr[k], feat[k], acc);
        out[tid] = acc;
    }
}

// ---------------------------------------------------------------------------
// Launch
// ---------------------------------------------------------------------------
extern "C" void kernel_launch(void* const* d_in, const int* in_sizes, int n_in,
                              void* d_out, int out_size) {
    const float* words   = (const float*)d_in[0];
    const int*   lengths = (const int*)  d_in[1];
    const float* h0w     = (const float*)d_in[2];
    const float* c0w     = (const float*)d_in[3];
    const float* h0p     = (const float*)d_in[4];
    const float* c0p     = (const float*)d_in[5];
    const float* h0q     = (const float*)d_in[6];
    const float* c0q     = (const float*)d_in[7];
    const float* wih_ctx = (const float*)d_in[8];
    const float* whh_ctx = (const float*)d_in[9];
    const float* bih_ctx = (const float*)d_in[10];
    const float* bhh_ctx = (const float*)d_in[11];
    const float* wih_tgt = (const float*)d_in[12];
    const float* whh_tgt = (const float*)d_in[13];
    const float* bih_tgt = (const float*)d_in[14];
    const float* bhh_tgt = (const float*)d_in[15];
    const float* wih_prv = (const float*)d_in[16];
    const float* whh_prv = (const float*)d_in[17];
    const float* bih_prv = (const float*)d_in[18];
    const float* bhh_prv = (const float*)d_in[19];
    const float* wih_pst = (const float*)d_in[20];
    const float* whh_pst = (const float*)d_in[21];
    const float* bih_pst = (const float*)d_in[22];
    const float* bhh_pst = (const float*)d_in[23];
    const float* fc_w    = (const float*)d_in[24];
    const float* fc_b    = (const float*)d_in[25];
    float* out = (float*)d_out;

    cudaFuncSetAttribute(rec_kernel, cudaFuncAttributeMaxDynamicSharedMemorySize,
                         REC_SMEM);

    // 1. sort sentences by length (desc) + per-step active counts
    sort_kernel<<<1, 256>>>(lengths);

    // 2. weight reorder (gate-interleaved float4)
    int pgrid = (H * K2 + 255) / 256;
    prep_kernel<<<pgrid, 256>>>(wih_ctx, whh_ctx, bih_ctx, bhh_ctx, 0);
    prep_kernel<<<pgrid, 256>>>(wih_tgt, whh_tgt, bih_tgt, bhh_tgt, 1);
    prep_kernel<<<pgrid, 256>>>(wih_prv, whh_prv, bih_prv, bhh_prv, 2);
    prep_kernel<<<pgrid, 256>>>(wih_pst, whh_pst, bih_pst, bhh_pst, 3);

    // 3. init phase-A state in rank order
    init_kernel<<<(S * H + 255) / 256, 256>>>(h0w, c0w);

    // 4. tgt input projection (independent of phase A)
    proj_kernel<<<W, 256>>>(words, 0, W, 1);

    // 5. phase A: 128 per-step fused GEMM+LSTM kernels over active sentences
    dim3 sgrid(H / KT, (S + MT - 1) / MT);   // (10, 65)
    for (int t = 0; t < W; t++)
        step_kernel<<<sgrid, 320>>>(words, lengths, t);

    // 6. tgt recurrence overwrites emb[MID] (steps = lengths[MID], device read)
    RecParams Ptgt;
    Ptgt.gx_sel = 0; Ptgt.set = 1;
    Ptgt.h0 = h0w + (long)MID * H; Ptgt.c0 = c0w + (long)MID * H;
    Ptgt.out_sel = 0; Ptgt.steps = 0; Ptgt.steps_dev = lengths + MID;
    rec_kernel<<<CL, 256, REC_SMEM>>>(Ptgt, Ptgt, 1);

    // 7. prev/post input projections (need complete emb incl. mid)
    proj_kernel<<<NSEQ_PREV, 256>>>(words, 1, NSEQ_PREV, 2);
    proj_kernel<<<NSEQ_PREV, 256>>>(words, 2, NSEQ_PREV, 3);

    // 8. prev + post recurrences, concurrent (two 4-CTA clusters)
    RecParams Pprev, Ppost;
    Pprev.gx_sel = 1; Pprev.set = 2; Pprev.h0 = h0p; Pprev.c0 = c0p;
    Pprev.out_sel = 1; Pprev.steps = NSEQ_PREV; Pprev.steps_dev = nullptr;
    Ppost.gx_sel = 2; Ppost.set = 3; Ppost.h0 = h0q; Ppost.c0 = c0q;
    Ppost.out_sel = 2; Ppost.steps = NSEQ_PREV; Ppost.steps_dev = nullptr;
    rec_kernel<<<2 * CL, 256, REC_SMEM>>>(Pprev, Ppost, 2);

    // 9. final FC -> d_out [200]
    fc_kernel<<<1, 256>>>(fc_w, fc_b, out);
}

// round 2
// speedup vs baseline: 1.0054x; 1.0054x over previous
#include <cuda_runtime.h>
#include <cstdint>
#include <math.h>

// Problem dimensions (fixed by the dataset)
#define H   200
#define S   1025
#define W   128
#define MID 512
#define NSEQ_PREV 513   // sentences 0..512
#define K2  (2*H)       // 400 : [x ; h]

// ---------------------------------------------------------------------------
// Device scratch (static globals: no allocation anywhere)
// ---------------------------------------------------------------------------
// Gate-interleaved weights: g_W4[set][kappa*400 + k] is float4 = (i,f,g,o)
// weights of hidden index kappa at input k (k<200 -> wih, k>=200 -> whh).
__device__ float4 g_W4[4][H * K2];   // 4 sets x 200 x 400 float4 = 5.1 MB
__device__ float4 g_b4[4][H];        // combined bias bih+bhh, interleaved
__device__ int    g_order[S];        // sentence indices sorted by length desc
__device__ int    g_cnt[W];          // cnt[t] = #sentences with len > t
__device__ float4 g_hA4[S * 50];     // phase-A hidden state (rank order), 200 f/row
__device__ float4 g_cA4[S * 50];     // phase-A cell state   (rank order)
__device__ float  g_emb[S * H];      // sentence embeddings (original order)
__device__ float4 g_GT4[W * H];          // tgt input projection
__device__ float4 g_GP4[NSEQ_PREV * H];  // prev input projection
__device__ float4 g_GQ4[NSEQ_PREV * H];  // post input projection (reversed)
__device__ float  g_prevh[H];
__device__ float  g_posth[H];

__device__ __forceinline__ float sigf(float x) { return 1.0f / (1.0f + expf(-x)); }

// ---------------------------------------------------------------------------
// Kernel 1: counting sort of sentences by length (descending) + active counts
// ---------------------------------------------------------------------------
__global__ void sort_kernel(const int* __restrict__ lengths) {
    __shared__ int hist[W + 1];
    __shared__ int cur[W + 1];
    int tid = threadIdx.x;
    for (int i = tid; i <= W; i += blockDim.x) hist[i] = 0;
    __syncthreads();
    for (int s = tid; s < S; s += blockDim.x) atomicAdd(&hist[lengths[s]], 1);
    __syncthreads();
    if (tid == 0) {
        int run = 0;
        for (int L = W; L >= 1; L--) { cur[L] = run; run += hist[L]; }
        for (int t = 0; t < W; t++) g_cnt[t] = (t == 0) ? run : cur[t];
    }
    __syncthreads();
    for (int s = tid; s < S; s += blockDim.x) {
        int r = atomicAdd(&cur[lengths[s]], 1);
        g_order[r] = s;   // rank among equal lengths nondeterministic but
                          // results are permutation-invariant
    }
}

// ---------------------------------------------------------------------------
// Kernel 2: ALL four weight sets reordered in one launch (blockIdx.y = set)
// ---------------------------------------------------------------------------
struct PrepArgs {
    const float* wih[4];
    const float* whh[4];
    const float* bih[4];
    const float* bhh[4];
};
__global__ void prep_kernel(PrepArgs pa) {
    int set = blockIdx.y;
    int idx = blockIdx.x * blockDim.x + threadIdx.x;
    if (idx >= H * K2) return;
    const float* wih = pa.wih[set];
    const float* whh = pa.whh[set];
    int kap = idx / K2;
    int k   = idx % K2;
    float4 v;
    if (k < H) {
        v.x = wih[(0 * H + kap) * H + k];
        v.y = wih[(1 * H + kap) * H + k];
        v.z = wih[(2 * H + kap) * H + k];
        v.w = wih[(3 * H + kap) * H + k];
    } else {
        int kk = k - H;
        v.x = whh[(0 * H + kap) * H + kk];
        v.y = whh[(1 * H + kap) * H + kk];
        v.z = whh[(2 * H + kap) * H + kk];
        v.w = whh[(3 * H + kap) * H + kk];
    }
    g_W4[set][idx] = v;
    if (k == 0) {
        const float* bih = pa.bih[set];
        const float* bhh = pa.bhh[set];
        float4 b;
        b.x = bih[0 * H + kap] + bhh[0 * H + kap];
        b.y = bih[1 * H + kap] + bhh[1 * H + kap];
        b.z = bih[2 * H + kap] + bhh[2 * H + kap];
        b.w = bih[3 * H + kap] + bhh[3 * H + kap];
        g_b4[set][kap] = b;
    }
}

// ---------------------------------------------------------------------------
// Kernel 3: init phase-A state in sorted-rank order
// ---------------------------------------------------------------------------
__global__ void init_kernel(const float* __restrict__ h0w,
                            const float* __restrict__ c0w) {
    int idx = blockIdx.x * blockDim.x + threadIdx.x;
    if (idx >= S * H) return;
    int r = idx / H, k = idx % H;
    int s = g_order[r];
    ((float*)g_hA4)[idx] = h0w[s * H + k];
    ((float*)g_cA4)[idx] = c0w[s * H + k];
}

// ---------------------------------------------------------------------------
// Kernel 4: one LSTM time step, register-tiled fused GEMM + update.
//   Tile: 32 rows x 32 kappa. 256 threads; each thread owns 4 rows x 1 kappa
//   x 4 gates (row interleave m = mth + 8*rr -> conflict-free LDS.128).
//   Inner iter: 4 LDG.128 (weights, 8-lane broadcast) + 4 LDS.128 -> 64 FMA.
// ---------------------------------------------------------------------------
#define MT 32
#define KT 32
#define RM 4
#define SMEM_STEP (MT * 101 * 16)   // 51712 B

__global__ __launch_bounds__(256) void step_kernel(const float* __restrict__ words,
                                                   const int* __restrict__ lengths,
                                                   int t) {
    int cnt = g_cnt[t];
    int mbase = blockIdx.y * MT;
    if (mbase >= cnt) return;

    extern __shared__ float4 Asm4[];   // [MT][101] : row stride 101 float4
    int tid = threadIdx.x;

    // Stage A tile as float4 (x from words via g_order; h from g_hA4)
    for (int idx = tid; idx < MT * 100; idx += 256) {
        int m = idx / 100, k4 = idx % 100;
        int r = mbase + m; if (r > S - 1) r = S - 1;
        float4 v;
        if (k4 < 50) {
            int s = g_order[r];
            v = ((const float4*)(words + ((long)s * W + t) * H))[k4];
        } else {
            v = g_hA4[r * 50 + (k4 - 50)];
        }
        Asm4[m * 101 + k4] = v;
    }
    __syncthreads();

    int mth = tid & 7;
    int kl  = tid >> 3;
    int kap = blockIdx.x * KT + kl;
    int kapc = (kap < H) ? kap : (H - 1);

    const float4* __restrict__ wr = &g_W4[0][kapc * K2];
    float4 b = g_b4[0][kapc];
    float4 acc[RM];
#pragma unroll
    for (int rr = 0; rr < RM; rr++) acc[rr] = b;

#pragma unroll 2
    for (int k4 = 0; k4 < 100; k4++) {
        float4 w0 = wr[k4 * 4 + 0];
        float4 w1 = wr[k4 * 4 + 1];
        float4 w2 = wr[k4 * 4 + 2];
        float4 w3 = wr[k4 * 4 + 3];
#pragma unroll
        for (int rr = 0; rr < RM; rr++) {
            float4 a = Asm4[(mth + 8 * rr) * 101 + k4];
            acc[rr].x = fmaf(w0.x, a.x, acc[rr].x);
            acc[rr].y = fmaf(w0.y, a.x, acc[rr].y);
            acc[rr].z = fmaf(w0.z, a.x, acc[rr].z);
            acc[rr].w = fmaf(w0.w, a.x, acc[rr].w);
            acc[rr].x = fmaf(w1.x, a.y, acc[rr].x);
            acc[rr].y = fmaf(w1.y, a.y, acc[rr].y);
            acc[rr].z = fmaf(w1.z, a.y, acc[rr].z);
            acc[rr].w = fmaf(w1.w, a.y, acc[rr].w);
            acc[rr].x = fmaf(w2.x, a.z, acc[rr].x);
            acc[rr].y = fmaf(w2.y, a.z, acc[rr].y);
            acc[rr].z = fmaf(w2.z, a.z, acc[rr].z);
            acc[rr].w = fmaf(w2.w, a.z, acc[rr].w);
            acc[rr].x = fmaf(w3.x, a.w, acc[rr].x);
            acc[rr].y = fmaf(w3.y, a.w, acc[rr].y);
            acc[rr].z = fmaf(w3.z, a.w, acc[rr].z);
            acc[rr].w = fmaf(w3.w, a.w, acc[rr].w);
        }
    }

    if (kap < H) {
#pragma unroll
        for (int rr = 0; rr < RM; rr++) {
            int r = mbase + mth + 8 * rr;
            if (r < cnt) {
                float ig = sigf(acc[rr].x);
                float fg = sigf(acc[rr].y);
                float gg = tanhf(acc[rr].z);
                float og = sigf(acc[rr].w);
                int off = r * H + kap;
                float c = fg * ((float*)g_cA4)[off] + ig * gg;
                float h = og * tanhf(c);
                ((float*)g_cA4)[off] = c;
                ((float*)g_hA4)[off] = h;
                int s = g_order[r];
                if (lengths[s] == t + 1) g_emb[s * H + kap] = h;
            }
        }
    }
}

// ---------------------------------------------------------------------------
// Kernel 5: input projections  out4[t][kap] = b4 + W_in . x(t)
//   x_sel: 0 = words[MID] -> g_GT4 ; 1 = emb forward -> g_GP4 ;
//          2 = emb reversed -> g_GQ4
// ---------------------------------------------------------------------------
__global__ void proj_kernel(const float* __restrict__ words, int x_sel, int T, int set) {
    int t = blockIdx.x;
    if (t >= T) return;
    const float* xbase;
    long xstride;
    float4* out;
    if (x_sel == 0)      { xbase = words + (long)MID * W * H; xstride =  H; out = g_GT4; }
    else if (x_sel == 1) { xbase = g_emb;                     xstride =  H; out = g_GP4; }
    else                 { xbase = g_emb + (long)(S - 1) * H; xstride = -H; out = g_GQ4; }

    __shared__ float xs[H];
    int tid = threadIdx.x;
    if (tid < H) xs[tid] = xbase[(long)t * xstride + tid];
    __syncthreads();
    if (tid >= H) return;
    int kap = tid;
    const float4* __restrict__ wr = &g_W4[set][kap * K2];
    float4 acc = g_b4[set][kap];
#pragma unroll 4
    for (int k = 0; k < H; k++) {
        float a = xs[k];
        float4 w = wr[k];
        acc.x = fmaf(w.x, a, acc.x);
        acc.y = fmaf(w.y, a, acc.y);
        acc.z = fmaf(w.z, a, acc.z);
        acc.w = fmaf(w.w, a, acc.w);
    }
    out[t * H + kap] = acc;
}

// ---------------------------------------------------------------------------
// Kernel 6: serial LSTM recurrence, 4-CTA cluster, whh slice resident in SMEM.
//   CTA r owns hidden indices [r*50, r*50+50) (all 4 gates, interleaved),
//   so the LSTM update is CTA-local; only h is broadcast via DSMEM per step.
// ---------------------------------------------------------------------------
#define CL 4
struct RecParams {
    int gx_sel;            // 0 g_GT4, 1 g_GP4, 2 g_GQ4
    int set;               // weight set index
    const float* h0;
    const float* c0;
    int out_sel;           // 0 -> g_emb[MID], 1 -> g_prevh, 2 -> g_posth
    int steps;             // fixed step count (if steps_dev == nullptr)
    const int* steps_dev;  // device override (tgt: &lengths[MID])
};

#define REC_SMEM (50 * H * 16 + 256 * 4 + 64 * 4 + 4 * 50 * 16)

__device__ __forceinline__ void cluster_sync_() {
    asm volatile("barrier.cluster.arrive.aligned;" ::: "memory");
    asm volatile("barrier.cluster.wait.aligned;" ::: "memory");
}

__global__ void __cluster_dims__(CL, 1, 1) __launch_bounds__(256, 1)
rec_kernel(RecParams p0, RecParams p1, int ncl) {
    int cid = blockIdx.x / CL;
    if (cid >= ncl) return;               // whole cluster exits together
    RecParams P = (cid == 0) ? p0 : p1;

    const float4* gx = (P.gx_sel == 0) ? g_GT4 : (P.gx_sel == 1) ? g_GP4 : g_GQ4;
    float* out = (P.out_sel == 0) ? (g_emb + (long)MID * H)
               : (P.out_sel == 1) ? g_prevh : g_posth;
    const float4* w4 = g_W4[P.set];

    extern __shared__ float smem[];
    float4* Wsm = (float4*)smem;                       // [50][200]
    float*  h_sm = (float*)(Wsm + 50 * H);             // [200] (pad 256)
    float*  c_sm = h_sm + 256;                         // [50]  (pad 64)
    float4* psum = (float4*)(c_sm + 64);               // [4][50]

    int tid = threadIdx.x;
    int r = blockIdx.x % CL;                           // cluster cta rank

    for (int idx = tid; idx < 50 * H; idx += 256) {
        int kl = idx / H, k = idx % H;
        Wsm[kl * H + k] = w4[(r * 50 + kl) * K2 + H + k];
    }
    for (int k = tid; k < H; k += 256) h_sm[k] = P.h0[k];
    if (tid < 50) c_sm[tid] = P.c0[r * 50 + tid];
    int steps = P.steps_dev ? P.steps_dev[0] : P.steps;
    __syncthreads();
    cluster_sync_();   // all CTAs' h_sm init done before anyone writes into it

    for (int t = 0; t < steps; t++) {
        if (tid < 200) {
            int c4 = tid & 3, kl = tid >> 2;
            float4 acc = make_float4(0.f, 0.f, 0.f, 0.f);
            const float4* wrow = &Wsm[kl * H + c4 * 50];
            const float* hp = &h_sm[c4 * 50];
#pragma unroll 10
            for (int k = 0; k < 50; k++) {
                float a = hp[k];
                float4 w = wrow[k];
                acc.x = fmaf(w.x, a, acc.x);
                acc.y = fmaf(w.y, a, acc.y);
                acc.z = fmaf(w.z, a, acc.z);
                acc.w = fmaf(w.w, a, acc.w);
            }
            psum[c4 * 50 + kl] = acc;
        }
        __syncthreads();
        if (tid < 50) {
            float4 g = gx[t * H + r * 50 + tid];
            float4 a0 = psum[0 * 50 + tid], a1 = psum[1 * 50 + tid];
            float4 a2 = psum[2 * 50 + tid], a3 = psum[3 * 50 + tid];
            g.x += a0.x + a1.x + a2.x + a3.x;
            g.y += a0.y + a1.y + a2.y + a3.y;
            g.z += a0.z + a1.z + a2.z + a3.z;
            g.w += a0.w + a1.w + a2.w + a3.w;
            float ig = sigf(g.x), fg = sigf(g.y), gg = tanhf(g.z), og = sigf(g.w);
            float cn = fg * c_sm[tid] + ig * gg;
            c_sm[tid] = cn;
            float hn = og * tanhf(cn);
            int hidx = r * 50 + tid;
            uint32_t laddr = (uint32_t)__cvta_generic_to_shared(&h_sm[hidx]);
#pragma unroll
            for (int tr = 0; tr < CL; tr++) {
                uint32_t raddr;
                asm volatile("mapa.shared::cluster.u32 %0, %1, %2;"
                             : "=r"(raddr) : "r"(laddr), "r"(tr));
                asm volatile("st.shared::cluster.f32 [%0], %1;"
                             :: "r"(raddr), "f"(hn) : "memory");
            }
        }
        cluster_sync_();   // release remote h writes / acquire for next GEMV
    }

    if (tid < 50) out[r * 50 + tid] = h_sm[r * 50 + tid];
}

// ---------------------------------------------------------------------------
// Kernel 7: final FC   out[j] = fc_b[j] + [prev;post] . fc_w[j, :]
// ---------------------------------------------------------------------------
__global__ void fc_kernel(const float* __restrict__ fcw,
                          const float* __restrict__ fcb,
                          float* __restrict__ out) {
    __shared__ float feat[K2];
    int tid = threadIdx.x;
    if (tid < H) { feat[tid] = g_prevh[tid]; feat[H + tid] = g_posth[tid]; }
    __syncthreads();
    if (tid < H) {
        float acc = fcb[tid];
        const float* wr = &fcw[tid * K2];
#pragma unroll 4
        for (int k = 0; k < K2; k++) acc = fmaf(wr[k], feat[k], acc);
        out[tid] = acc;
    }
}

// ---------------------------------------------------------------------------
// Launch
// ---------------------------------------------------------------------------
extern "C" void kernel_launch(void* const* d_in, const int* in_sizes, int n_in,
                              void* d_out, int out_size) {
    const float* words   = (const float*)d_in[0];
    const int*   lengths = (const int*)  d_in[1];
    const float* h0w     = (const float*)d_in[2];
    const float* c0w     = (const float*)d_in[3];
    const float* h0p     = (const float*)d_in[4];
    const float* c0p     = (const float*)d_in[5];
    const float* h0q     = (const float*)d_in[6];
    const float* c0q     = (const float*)d_in[7];
    const float* fc_w    = (const float*)d_in[24];
    const float* fc_b    = (const float*)d_in[25];
    float* out = (float*)d_out;

    cudaFuncSetAttribute(rec_kernel, cudaFuncAttributeMaxDynamicSharedMemorySize,
                         REC_SMEM);
    cudaFuncSetAttribute(step_kernel, cudaFuncAttributeMaxDynamicSharedMemorySize,
                         SMEM_STEP);

    // 1. sort sentences by length (desc) + per-step active counts
    sort_kernel<<<1, 256>>>(lengths);

    // 2. all weight reorders in ONE launch (keeps ncu -s 5 on a step kernel)
    PrepArgs pa;
    for (int i = 0; i < 4; i++) {
        pa.wih[i] = (const float*)d_in[8 + 4 * i];
        pa.whh[i] = (const float*)d_in[9 + 4 * i];
        pa.bih[i] = (const float*)d_in[10 + 4 * i];
        pa.bhh[i] = (const float*)d_in[11 + 4 * i];
    }
    dim3 pgrid((H * K2 + 255) / 256, 4);
    prep_kernel<<<pgrid, 256>>>(pa);

    // 3. init phase-A state in rank order
    init_kernel<<<(S * H + 255) / 256, 256>>>(h0w, c0w);

    // 4. tgt input projection (independent of phase A)
    proj_kernel<<<W, 256>>>(words, 0, W, 1);

    // 5. phase A: 128 per-step fused GEMM+LSTM kernels (launch #5 = t0, #6 = t1)
    dim3 sgrid((H + KT - 1) / KT, (S + MT - 1) / MT);   // (7, 33)
    for (int t = 0; t < W; t++)
        step_kernel<<<sgrid, 256, SMEM_STEP>>>(words, lengths, t);

    // 6. tgt recurrence overwrites emb[MID] (steps = lengths[MID], device read)
    RecParams Ptgt;
    Ptgt.gx_sel = 0; Ptgt.set = 1;
    Ptgt.h0 = h0w + (long)MID * H; Ptgt.c0 = c0w + (long)MID * H;
    Ptgt.out_sel = 0; Ptgt.steps = 0; Ptgt.steps_dev = lengths + MID;
    rec_kernel<<<CL, 256, REC_SMEM>>>(Ptgt, Ptgt, 1);

    // 7. prev/post input projections (need complete emb incl. mid)
    proj_kernel<<<NSEQ_PREV, 256>>>(words, 1, NSEQ_PREV, 2);
    proj_kernel<<<NSEQ_PREV, 256>>>(words, 2, NSEQ_PREV, 3);

    // 8. prev + post recurrences, concurrent (two 4-CTA clusters)
    RecParams Pprev, Ppost;
    Pprev.gx_sel = 1; Pprev.set = 2; Pprev.h0 = h0p; Pprev.c0 = c0p;
    Pprev.out_sel = 1; Pprev.steps = NSEQ_PREV; Pprev.steps_dev = nullptr;
    Ppost.gx_sel = 2; Ppost.set = 3; Ppost.h0 = h0q; Ppost.c0 = c0q;
    Ppost.out_sel = 2; Ppost.steps = NSEQ_PREV; Ppost.steps_dev = nullptr;
    rec_kernel<<<2 * CL, 256, REC_SMEM>>>(Pprev, Ppost, 2);

    // 9. final FC -> d_out [200]
    fc_kernel<<<1, 256>>>(fc_w, fc_b, out);
}

// round 7
// speedup vs baseline: 1.2807x; 1.2738x over previous
#include <cuda_runtime.h>
#include <cstdint>
#include <math.h>

// Problem dimensions (fixed by the dataset)
#define H   200
#define S   1025
#define W   128
#define MID 512
#define NSEQ_PREV 513   // sentences 0..512
#define K2  (2*H)       // 400 : [x ; h]

// ---------------------------------------------------------------------------
// Device scratch (static globals: no allocation anywhere)
// ---------------------------------------------------------------------------
__device__ float4 g_W4[4][H * K2];   // gate-interleaved weights (i,f,g,o per k)
__device__ float4 g_b4[4][H];        // combined bias bih+bhh, interleaved
__device__ int    g_order[S];        // sentence indices sorted by length desc
__device__ int    g_cnt[W];          // cnt[t] = #sentences with len > t
__device__ float4 g_hA4[2][S * 50];  // DOUBLE-BUFFERED hidden state (rank order)
__device__ float4 g_cA4[S * 50];     // cell state (one owner thread per step)
__device__ float  g_emb[S * H];      // sentence embeddings (original order)
__device__ float4 g_GT4[W * H];          // tgt input projection
__device__ float4 g_GP4[NSEQ_PREV * H];  // prev input projection
__device__ float4 g_GQ4[NSEQ_PREV * H];  // post input projection (reversed)
__device__ float  g_prevh[H];
__device__ float  g_posth[H];

__device__ __forceinline__ float sigf(float x) { return 1.0f / (1.0f + expf(-x)); }

// ---------------------------------------------------------------------------
// Kernel 1: counting sort of sentences by length (descending) + active counts
// ---------------------------------------------------------------------------
__global__ void sort_kernel(const int* __restrict__ lengths) {
    __shared__ int hist[W + 1];
    __shared__ int cur[W + 1];
    int tid = threadIdx.x;
    for (int i = tid; i <= W; i += blockDim.x) hist[i] = 0;
    __syncthreads();
    for (int s = tid; s < S; s += blockDim.x) atomicAdd(&hist[lengths[s]], 1);
    __syncthreads();
    if (tid == 0) {
        int run = 0;
        for (int L = W; L >= 1; L--) { cur[L] = run; run += hist[L]; }
        for (int t = 0; t < W; t++) g_cnt[t] = (t == 0) ? run : cur[t];
    }
    __syncthreads();
    for (int s = tid; s < S; s += blockDim.x) {
        int r = atomicAdd(&cur[lengths[s]], 1);
        g_order[r] = s;   // rank among equal lengths nondeterministic but
                          // results are permutation-invariant
    }
}

// ---------------------------------------------------------------------------
// Kernel 2: ALL four weight sets reordered in one launch (blockIdx.y = set)
// ---------------------------------------------------------------------------
struct PrepArgs {
    const float* wih[4];
    const float* whh[4];
    const float* bih[4];
    const float* bhh[4];
};
__global__ void prep_kernel(PrepArgs pa) {
    int set = blockIdx.y;
    int idx = blockIdx.x * blockDim.x + threadIdx.x;
    if (idx >= H * K2) return;
    const float* wih = pa.wih[set];
    const float* whh = pa.whh[set];
    int kap = idx / K2;
    int k   = idx % K2;
    float4 v;
    if (k < H) {
        v.x = wih[(0 * H + kap) * H + k];
        v.y = wih[(1 * H + kap) * H + k];
        v.z = wih[(2 * H + kap) * H + k];
        v.w = wih[(3 * H + kap) * H + k];
    } else {
        int kk = k - H;
        v.x = whh[(0 * H + kap) * H + kk];
        v.y = whh[(1 * H + kap) * H + kk];
        v.z = whh[(2 * H + kap) * H + kk];
        v.w = whh[(3 * H + kap) * H + kk];
    }
    g_W4[set][idx] = v;
    if (k == 0) {
        const float* bih = pa.bih[set];
        const float* bhh = pa.bhh[set];
        float4 b;
        b.x = bih[0 * H + kap] + bhh[0 * H + kap];
        b.y = bih[1 * H + kap] + bhh[1 * H + kap];
        b.z = bih[2 * H + kap] + bhh[2 * H + kap];
        b.w = bih[3 * H + kap] + bhh[3 * H + kap];
        g_b4[set][kap] = b;
    }
}

// ---------------------------------------------------------------------------
// Kernel 3: init phase-A state (rank order, buffer 0)
// ---------------------------------------------------------------------------
__global__ void init_kernel(const float* __restrict__ h0w,
                            const float* __restrict__ c0w) {
    int idx = blockIdx.x * blockDim.x + threadIdx.x;
    if (idx >= S * H) return;
    int r = idx / H, k = idx % H;
    int s = g_order[r];
    ((float*)g_hA4[0])[idx] = h0w[s * H + k];
    ((float*)g_cA4)[idx]    = c0w[s * H + k];
}

// ---------------------------------------------------------------------------
// Kernel 4: one LSTM time step (PER-STEP LAUNCH — ordering by launch
//   boundary, correct by construction). Grid-stride over 16x32 tiles with a
//   FIXED grid of 296 CTAs (2/SM) to kill last-wave raggedness. h is
//   double-buffered (read t&1, write (t&1)^1): no intra-step h race. c is
//   touched by exactly one thread per step: no race.
// ---------------------------------------------------------------------------
#define G_STEP 296
#define MT 16
#define KT 32
#define NKT 7                        // ceil(200/32)
#define SMEM_A (MT * 101 * 16)       // 25856 B

__global__ __launch_bounds__(256, 2) void step_kernel(const float* __restrict__ words,
                                                      const int* __restrict__ lengths,
                                                      int t) {
    extern __shared__ float4 Asm4[];   // [MT][101]
    int tid = threadIdx.x;
    int mth = tid & 7;
    int kl  = tid >> 3;                // 0..31

    const float4* __restrict__ h_in = g_hA4[t & 1];
    float4* __restrict__       h_out = g_hA4[(t & 1) ^ 1];
    int cnt = g_cnt[t];
    int nrt = (cnt + MT - 1) / MT;
    int tiles = nrt * NKT;

    for (int tk = blockIdx.x; tk < tiles; tk += G_STEP) {
        int rt = tk % nrt;
        int kt = tk / nrt;
        int mbase = rt * MT;

        // stage A tile: [x_t ; h(t-1)] for 16 rows
        for (int idx = tid; idx < MT * 100; idx += 256) {
            int m = idx / 100, k4 = idx % 100;
            int r = mbase + m; if (r > S - 1) r = S - 1;
            float4 v;
            if (k4 < 50) {
                int s = g_order[r];
                v = ((const float4*)(words + ((long)s * W + t) * H))[k4];
            } else {
                v = h_in[r * 50 + (k4 - 50)];
            }
            Asm4[m * 101 + k4] = v;
        }
        __syncthreads();

        int kap  = kt * KT + kl;
        int kapc = (kap < H) ? kap : (H - 1);
        const float4* __restrict__ wr = &g_W4[0][kapc * K2];
        float4 b = g_b4[0][kapc];
        float4 acc0 = b, acc1 = b;

#pragma unroll 2
        for (int k4 = 0; k4 < 100; k4++) {
            float4 w0 = wr[k4 * 4 + 0];
            float4 w1 = wr[k4 * 4 + 1];
            float4 w2 = wr[k4 * 4 + 2];
            float4 w3 = wr[k4 * 4 + 3];
            float4 a0 = Asm4[mth * 101 + k4];
            float4 a1 = Asm4[(mth + 8) * 101 + k4];
            acc0.x = fmaf(w0.x, a0.x, acc0.x); acc0.y = fmaf(w0.y, a0.x, acc0.y);
            acc0.z = fmaf(w0.z, a0.x, acc0.z); acc0.w = fmaf(w0.w, a0.x, acc0.w);
            acc1.x = fmaf(w0.x, a1.x, acc1.x); acc1.y = fmaf(w0.y, a1.x, acc1.y);
            acc1.z = fmaf(w0.z, a1.x, acc1.z); acc1.w = fmaf(w0.w, a1.x, acc1.w);
            acc0.x = fmaf(w1.x, a0.y, acc0.x); acc0.y = fmaf(w1.y, a0.y, acc0.y);
            acc0.z = fmaf(w1.z, a0.y, acc0.z); acc0.w = fmaf(w1.w, a0.y, acc0.w);
            acc1.x = fmaf(w1.x, a1.y, acc1.x); acc1.y = fmaf(w1.y, a1.y, acc1.y);
            acc1.z = fmaf(w1.z, a1.y, acc1.z); acc1.w = fmaf(w1.w, a1.y, acc1.w);
            acc0.x = fmaf(w2.x, a0.z, acc0.x); acc0.y = fmaf(w2.y, a0.z, acc0.y);
            acc0.z = fmaf(w2.z, a0.z, acc0.z); acc0.w = fmaf(w2.w, a0.z, acc0.w);
            acc1.x = fmaf(w2.x, a1.z, acc1.x); acc1.y = fmaf(w2.y, a1.z, acc1.y);
            acc1.z = fmaf(w2.z, a1.z, acc1.z); acc1.w = fmaf(w2.w, a1.z, acc1.w);
            acc0.x = fmaf(w3.x, a0.w, acc0.x); acc0.y = fmaf(w3.y, a0.w, acc0.y);
            acc0.z = fmaf(w3.z, a0.w, acc0.z); acc0.w = fmaf(w3.w, a0.w, acc0.w);
            acc1.x = fmaf(w3.x, a1.w, acc1.x); acc1.y = fmaf(w3.y, a1.w, acc1.y);
            acc1.z = fmaf(w3.z, a1.w, acc1.z); acc1.w = fmaf(w3.w, a1.w, acc1.w);
        }

        if (kap < H) {
#pragma unroll
            for (int rr = 0; rr < 2; rr++) {
                float4 acc = rr ? acc1 : acc0;
                int r = mbase + mth + 8 * rr;
                if (r < cnt) {
                    float ig = sigf(acc.x);
                    float fg = sigf(acc.y);
                    float gg = tanhf(acc.z);
                    float og = sigf(acc.w);
                    int off = r * H + kap;
                    float c = fg * ((float*)g_cA4)[off] + ig * gg;
                    float h = og * tanhf(c);
                    ((float*)g_cA4)[off] = c;
                    ((float*)h_out)[off] = h;
                    int s = g_order[r];
                    if (lengths[s] == t + 1) g_emb[s * H + kap] = h;
                }
            }
        }
        __syncthreads();   // Asm4 reads done before next tile's staging
    }
}

// ---------------------------------------------------------------------------
// Kernel 5: input projections  out4[t][kap] = b4 + W_in . x(t)
// ---------------------------------------------------------------------------
__global__ void proj_kernel(const float* __restrict__ words, int x_sel, int T, int set) {
    int t = blockIdx.x;
    if (t >= T) return;
    const float* xbase;
    long xstride;
    float4* out;
    if (x_sel == 0)      { xbase = words + (long)MID * W * H; xstride =  H; out = g_GT4; }
    else if (x_sel == 1) { xbase = g_emb;                     xstride =  H; out = g_GP4; }
    else                 { xbase = g_emb + (long)(S - 1) * H; xstride = -H; out = g_GQ4; }

    __shared__ float xs[H];
    int tid = threadIdx.x;
    if (tid < H) xs[tid] = xbase[(long)t * xstride + tid];
    __syncthreads();
    if (tid >= H) return;
    int kap = tid;
    const float4* __restrict__ wr = &g_W4[set][kap * K2];
    float4 acc = g_b4[set][kap];
#pragma unroll 4
    for (int k = 0; k < H; k++) {
        float a = xs[k];
        float4 w = wr[k];
        acc.x = fmaf(w.x, a, acc.x);
        acc.y = fmaf(w.y, a, acc.y);
        acc.z = fmaf(w.z, a, acc.z);
        acc.w = fmaf(w.w, a, acc.w);
    }
    out[t * H + kap] = acc;
}

// ---------------------------------------------------------------------------
// Kernel 6: serial LSTM recurrence, 4-CTA cluster, whh slice in SMEM
// ---------------------------------------------------------------------------
#define CL 4
struct RecParams {
    int gx_sel;
    int set;
    const float* h0;
    const float* c0;
    int out_sel;
    int steps;
    const int* steps_dev;
};

#define REC_SMEM (50 * H * 16 + 256 * 4 + 64 * 4 + 4 * 50 * 16)

__device__ __forceinline__ void cluster_sync_() {
    asm volatile("barrier.cluster.arrive.aligned;" ::: "memory");
    asm volatile("barrier.cluster.wait.aligned;" ::: "memory");
}

__global__ void __cluster_dims__(CL, 1, 1) __launch_bounds__(256, 1)
rec_kernel(RecParams p0, RecParams p1, int ncl) {
    int cid = blockIdx.x / CL;
    if (cid >= ncl) return;
    RecParams P = (cid == 0) ? p0 : p1;

    const float4* gx = (P.gx_sel == 0) ? g_GT4 : (P.gx_sel == 1) ? g_GP4 : g_GQ4;
    float* out = (P.out_sel == 0) ? (g_emb + (long)MID * H)
               : (P.out_sel == 1) ? g_prevh : g_posth;
    const float4* w4 = g_W4[P.set];

    extern __shared__ float smem[];
    float4* Wsm = (float4*)smem;                       // [50][200]
    float*  h_sm = (float*)(Wsm + 50 * H);             // [200] (pad 256)
    float*  c_sm = h_sm + 256;                         // [50]  (pad 64)
    float4* psum = (float4*)(c_sm + 64);               // [4][50]

    int tid = threadIdx.x;
    int r = blockIdx.x % CL;

    for (int idx = tid; idx < 50 * H; idx += 256) {
        int kl = idx / H, k = idx % H;
        Wsm[kl * H + k] = w4[(r * 50 + kl) * K2 + H + k];
    }
    for (int k = tid; k < H; k += 256) h_sm[k] = P.h0[k];
    if (tid < 50) c_sm[tid] = P.c0[r * 50 + tid];
    int steps = P.steps_dev ? P.steps_dev[0] : P.steps;
    __syncthreads();
    cluster_sync_();

    for (int t = 0; t < steps; t++) {
        if (tid < 200) {
            int c4 = tid & 3, kl = tid >> 2;
            float4 acc = make_float4(0.f, 0.f, 0.f, 0.f);
            const float4* wrow = &Wsm[kl * H + c4 * 50];
            const float* hp = &h_sm[c4 * 50];
#pragma unroll 10
            for (int k = 0; k < 50; k++) {
                float a = hp[k];
                float4 w = wrow[k];
                acc.x = fmaf(w.x, a, acc.x);
                acc.y = fmaf(w.y, a, acc.y);
                acc.z = fmaf(w.z, a, acc.z);
                acc.w = fmaf(w.w, a, acc.w);
            }
            psum[c4 * 50 + kl] = acc;
        }
        __syncthreads();
        if (tid < 50) {
            float4 g = gx[t * H + r * 50 + tid];
            float4 a0 = psum[0 * 50 + tid], a1 = psum[1 * 50 + tid];
            float4 a2 = psum[2 * 50 + tid], a3 = psum[3 * 50 + tid];
            g.x += a0.x + a1.x + a2.x + a3.x;
            g.y += a0.y + a1.y + a2.y + a3.y;
            g.z += a0.z + a1.z + a2.z + a3.z;
            g.w += a0.w + a1.w + a2.w + a3.w;
            float ig = sigf(g.x), fg = sigf(g.y), gg = tanhf(g.z), og = sigf(g.w);
            float cn = fg * c_sm[tid] + ig * gg;
            c_sm[tid] = cn;
            float hn = og * tanhf(cn);
            int hidx = r * 50 + tid;
            uint32_t laddr = (uint32_t)__cvta_generic_to_shared(&h_sm[hidx]);
#pragma unroll
            for (int tr = 0; tr < CL; tr++) {
                uint32_t raddr;
                asm volatile("mapa.shared::cluster.u32 %0, %1, %2;"
                             : "=r"(raddr) : "r"(laddr), "r"(tr));
                asm volatile("st.shared::cluster.f32 [%0], %1;"
                             :: "r"(raddr), "f"(hn) : "memory");
            }
        }
        cluster_sync_();
    }

    if (tid < 50) out[r * 50 + tid] = h_sm[r * 50 + tid];
}

// ---------------------------------------------------------------------------
// Kernel 7: final FC
// ---------------------------------------------------------------------------
__global__ void fc_kernel(const float* __restrict__ fcw,
                          const float* __restrict__ fcb,
                          float* __restrict__ out) {
    __shared__ float feat[K2];
    int tid = threadIdx.x;
    if (tid < H) { feat[tid] = g_prevh[tid]; feat[H + tid] = g_posth[tid]; }
    __syncthreads();
    if (tid < H) {
        float acc = fcb[tid];
        const float* wr = &fcw[tid * K2];
#pragma unroll 4
        for (int k = 0; k < K2; k++) acc = fmaf(wr[k], feat[k], acc);
        out[tid] = acc;
    }
}

// ---------------------------------------------------------------------------
// Launch
// ---------------------------------------------------------------------------
extern "C" void kernel_launch(void* const* d_in, const int* in_sizes, int n_in,
                              void* d_out, int out_size) {
    const float* words   = (const float*)d_in[0];
    const int*   lengths = (const int*)  d_in[1];
    const float* h0w     = (const float*)d_in[2];
    const float* c0w     = (const float*)d_in[3];
    const float* h0p     = (const float*)d_in[4];
    const float* c0p     = (const float*)d_in[5];
    const float* h0q     = (const float*)d_in[6];
    const float* c0q     = (const float*)d_in[7];
    const float* fc_w    = (const float*)d_in[24];
    const float* fc_b    = (const float*)d_in[25];
    float* out = (float*)d_out;

    cudaFuncSetAttribute(rec_kernel, cudaFuncAttributeMaxDynamicSharedMemorySize,
                         REC_SMEM);
    cudaFuncSetAttribute(step_kernel, cudaFuncAttributeMaxDynamicSharedMemorySize,
                         SMEM_A);

    // 1. sort sentences by length (desc) + per-step active counts
    sort_kernel<<<1, 256>>>(lengths);

    // 2. all weight reorders in ONE launch
    PrepArgs pa;
    for (int i = 0; i < 4; i++) {
        pa.wih[i] = (const float*)d_in[8 + 4 * i];
        pa.whh[i] = (const float*)d_in[9 + 4 * i];
        pa.bih[i] = (const float*)d_in[10 + 4 * i];
        pa.bhh[i] = (const float*)d_in[11 + 4 * i];
    }
    dim3 pgrid((H * K2 + 255) / 256, 4);
    prep_kernel<<<pgrid, 256>>>(pa);

    // 3. init state (buffer 0)
    init_kernel<<<(S * H + 255) / 256, 256>>>(h0w, c0w);

    // 4. tgt input projection (slot #3)
    proj_kernel<<<W, 256>>>(words, 0, W, 1);

    // 5. phase A: 128 per-step launches, grid-stride tiles on fixed 296 CTAs
    //    (slot #4 = t0, slot #5 = t1 -> ncu -s 5 captures step t1)
    for (int t = 0; t < W; t++)
        step_kernel<<<G_STEP, 256, SMEM_A>>>(words, lengths, t);

    // 6. tgt recurrence overwrites emb[MID]
    RecParams Ptgt;
    Ptgt.gx_sel = 0; Ptgt.set = 1;
    Ptgt.h0 = h0w + (long)MID * H; Ptgt.c0 = c0w + (long)MID * H;
    Ptgt.out_sel = 0; Ptgt.steps = 0; Ptgt.steps_dev = lengths + MID;
    rec_kernel<<<CL, 256, REC_SMEM>>>(Ptgt, Ptgt, 1);

    // 7. prev/post input projections
    proj_kernel<<<NSEQ_PREV, 256>>>(words, 1, NSEQ_PREV, 2);
    proj_kernel<<<NSEQ_PREV, 256>>>(words, 2, NSEQ_PREV, 3);

    // 8. prev + post recurrences, concurrent
    RecParams Pprev, Ppost;
    Pprev.gx_sel = 1; Pprev.set = 2; Pprev.h0 = h0p; Pprev.c0 = c0p;
    Pprev.out_sel = 1; Pprev.steps = NSEQ_PREV; Pprev.steps_dev = nullptr;
    Ppost.gx_sel = 2; Ppost.set = 3; Ppost.h0 = h0q; Ppost.c0 = c0q;
    Ppost.out_sel = 2; Ppost.steps = NSEQ_PREV; Ppost.steps_dev = nullptr;
    rec_kernel<<<2 * CL, 256, REC_SMEM>>>(Pprev, Ppost, 2);

    // 9. final FC -> d_out [200]
    fc_kernel<<<1, 256>>>(fc_w, fc_b, out);
}

// round 11
// speedup vs baseline: 1.4151x; 1.1049x over previous
#include <cuda_runtime.h>
#include <cstdint>
#include <math.h>

// Problem dimensions (fixed by the dataset)
#define H   200
#define S   1025
#define W   128
#define MID 512
#define NSEQ_PREV 513   // sentences 0..512
#define K2  (2*H)       // 400 : [x ; h]

// ---------------------------------------------------------------------------
// Device scratch (static globals: no allocation anywhere)
// ---------------------------------------------------------------------------
__device__ float4 g_W4[4][H * K2];   // gate-interleaved weights (i,f,g,o per k)
__device__ float4 g_b4[4][H];        // combined bias bih+bhh, interleaved
__device__ int    g_order[S];        // sentence indices sorted by length desc
__device__ int    g_cnt[W];          // cnt[t] = #sentences with len > t
__device__ int    g_off[W + 1];      // prefix sums of cnt (ragged GX offsets)
__device__ float4 g_hA4[2][S * 50];  // DOUBLE-BUFFERED hidden state (rank order)
__device__ float4 g_cA4[S * 50];     // cell state (one owner thread per step)
__device__ float  g_emb[S * H];      // sentence embeddings (original order)
// Precomputed input projection for ALL valid (t, rank) pairs, ragged layout:
// row (g_off[t] + r) holds  b + Wih . x[g_order[r]][t]  as H float4 gates.
__device__ float4 g_GX4[(size_t)S * W * H];   // worst case 131200 rows (420MB)
__device__ float4 g_GT4[W * H];          // tgt input projection
__device__ float4 g_GP4[NSEQ_PREV * H];  // prev input projection
__device__ float4 g_GQ4[NSEQ_PREV * H];  // post input projection (reversed)
__device__ float  g_prevh[H];
__device__ float  g_posth[H];

__device__ __forceinline__ float sigf(float x) { return 1.0f / (1.0f + expf(-x)); }

// ---------------------------------------------------------------------------
// Kernel 1: counting sort by length (desc) + active counts + prefix offsets
// ---------------------------------------------------------------------------
__global__ void sort_kernel(const int* __restrict__ lengths) {
    __shared__ int hist[W + 1];
    __shared__ int cur[W + 1];
    int tid = threadIdx.x;
    for (int i = tid; i <= W; i += blockDim.x) hist[i] = 0;
    __syncthreads();
    for (int s = tid; s < S; s += blockDim.x) atomicAdd(&hist[lengths[s]], 1);
    __syncthreads();
    if (tid == 0) {
        int run = 0;
        for (int L = W; L >= 1; L--) { cur[L] = run; run += hist[L]; }
        int off = 0;
        for (int t = 0; t < W; t++) {
            int c = (t == 0) ? run : cur[t];
            g_cnt[t] = c;
            g_off[t] = off;
            off += c;
        }
        g_off[W] = off;
    }
    __syncthreads();
    for (int s = tid; s < S; s += blockDim.x) {
        int r = atomicAdd(&cur[lengths[s]], 1);
        g_order[r] = s;   // rank among equal lengths nondeterministic but
                          // results are permutation-invariant
    }
}

// ---------------------------------------------------------------------------
// Kernel 2: ALL four weight sets reordered in one launch (blockIdx.y = set)
// ---------------------------------------------------------------------------
struct PrepArgs {
    const float* wih[4];
    const float* whh[4];
    const float* bih[4];
    const float* bhh[4];
};
__global__ void prep_kernel(PrepArgs pa) {
    int set = blockIdx.y;
    int idx = blockIdx.x * blockDim.x + threadIdx.x;
    if (idx >= H * K2) return;
    const float* wih = pa.wih[set];
    const float* whh = pa.whh[set];
    int kap = idx / K2;
    int k   = idx % K2;
    float4 v;
    if (k < H) {
        v.x = wih[(0 * H + kap) * H + k];
        v.y = wih[(1 * H + kap) * H + k];
        v.z = wih[(2 * H + kap) * H + k];
        v.w = wih[(3 * H + kap) * H + k];
    } else {
        int kk = k - H;
        v.x = whh[(0 * H + kap) * H + kk];
        v.y = whh[(1 * H + kap) * H + kk];
        v.z = whh[(2 * H + kap) * H + kk];
        v.w = whh[(3 * H + kap) * H + kk];
    }
    g_W4[set][idx] = v;
    if (k == 0) {
        const float* bih = pa.bih[set];
        const float* bhh = pa.bhh[set];
        float4 b;
        b.x = bih[0 * H + kap] + bhh[0 * H + kap];
        b.y = bih[1 * H + kap] + bhh[1 * H + kap];
        b.z = bih[2 * H + kap] + bhh[2 * H + kap];
        b.w = bih[3 * H + kap] + bhh[3 * H + kap];
        g_b4[set][kap] = b;
    }
}

// ---------------------------------------------------------------------------
// Kernel 3: init phase-A state (rank order, buffer 0)
// ---------------------------------------------------------------------------
__global__ void init_kernel(const float* __restrict__ h0w,
                            const float* __restrict__ c0w) {
    int idx = blockIdx.x * blockDim.x + threadIdx.x;
    if (idx >= S * H) return;
    int r = idx / H, k = idx % H;
    int s = g_order[r];
    ((float*)g_hA4[0])[idx] = h0w[s * H + k];
    ((float*)g_cA4)[idx]    = c0w[s * H + k];
}

// ---------------------------------------------------------------------------
// Kernel 4: GX precompute — fully parallel ragged GEMM (no serial dep):
//   GX[g_off[t]+r][kap] = b + Wih . x[g_order[r]][t]   for r < cnt[t].
//   Tile 16 rows x 32 kappa; grid (7 kap-tiles, 65 row-tiles, 128 steps).
// ---------------------------------------------------------------------------
#define MT 16
#define KT 32
#define NKT 7                        // ceil(200/32)

__global__ __launch_bounds__(256) void gx_kernel(const float* __restrict__ words) {
    int t = blockIdx.z;
    int cnt = g_cnt[t];
    int mbase = blockIdx.y * MT;
    if (mbase >= cnt) return;

    __shared__ float4 Xs[MT * 51];     // [16][50] +1 pad
    int tid = threadIdx.x;
    int mth = tid & 7;
    int kl  = tid >> 3;

    for (int idx = tid; idx < MT * 50; idx += 256) {
        int m = idx / 50, k4 = idx % 50;
        int r = mbase + m; if (r > cnt - 1) r = cnt - 1;
        int s = g_order[r];
        Xs[m * 51 + k4] = ((const float4*)(words + ((long)s * W + t) * H))[k4];
    }
    __syncthreads();

    int kap  = blockIdx.x * KT + kl;
    int kapc = (kap < H) ? kap : (H - 1);
    const float4* __restrict__ wr = &g_W4[0][kapc * K2];   // Wih rows: k in [0,H)
    float4 b = g_b4[0][kapc];
    float4 acc0 = b, acc1 = b;

#pragma unroll 2
    for (int k4 = 0; k4 < 50; k4++) {
        float4 w0 = wr[k4 * 4 + 0];
        float4 w1 = wr[k4 * 4 + 1];
        float4 w2 = wr[k4 * 4 + 2];
        float4 w3 = wr[k4 * 4 + 3];
        float4 a0 = Xs[mth * 51 + k4];
        float4 a1 = Xs[(mth + 8) * 51 + k4];
        acc0.x = fmaf(w0.x, a0.x, acc0.x); acc0.y = fmaf(w0.y, a0.x, acc0.y);
        acc0.z = fmaf(w0.z, a0.x, acc0.z); acc0.w = fmaf(w0.w, a0.x, acc0.w);
        acc1.x = fmaf(w0.x, a1.x, acc1.x); acc1.y = fmaf(w0.y, a1.x, acc1.y);
        acc1.z = fmaf(w0.z, a1.x, acc1.z); acc1.w = fmaf(w0.w, a1.x, acc1.w);
        acc0.x = fmaf(w1.x, a0.y, acc0.x); acc0.y = fmaf(w1.y, a0.y, acc0.y);
        acc0.z = fmaf(w1.z, a0.y, acc0.z); acc0.w = fmaf(w1.w, a0.y, acc0.w);
        acc1.x = fmaf(w1.x, a1.y, acc1.x); acc1.y = fmaf(w1.y, a1.y, acc1.y);
        acc1.z = fmaf(w1.z, a1.y, acc1.z); acc1.w = fmaf(w1.w, a1.y, acc1.w);
        acc0.x = fmaf(w2.x, a0.z, acc0.x); acc0.y = fmaf(w2.y, a0.z, acc0.y);
        acc0.z = fmaf(w2.z, a0.z, acc0.z); acc0.w = fmaf(w2.w, a0.z, acc0.w);
        acc1.x = fmaf(w2.x, a1.z, acc1.x); acc1.y = fmaf(w2.y, a1.z, acc1.y);
        acc1.z = fmaf(w2.z, a1.z, acc1.z); acc1.w = fmaf(w2.w, a1.z, acc1.w);
        acc0.x = fmaf(w3.x, a0.w, acc0.x); acc0.y = fmaf(w3.y, a0.w, acc0.y);
        acc0.z = fmaf(w3.z, a0.w, acc0.z); acc0.w = fmaf(w3.w, a0.w, acc0.w);
        acc1.x = fmaf(w3.x, a1.w, acc1.x); acc1.y = fmaf(w3.y, a1.w, acc1.y);
        acc1.z = fmaf(w3.z, a1.w, acc1.z); acc1.w = fmaf(w3.w, a1.w, acc1.w);
    }

    if (kap < H) {
        long base = g_off[t];
#pragma unroll
        for (int rr = 0; rr < 2; rr++) {
            int r = mbase + mth + 8 * rr;
            if (r < cnt)
                g_GX4[(base + r) * H + kap] = rr ? acc1 : acc0;
        }
    }
}

// ---------------------------------------------------------------------------
// Kernel 5: one LSTM time step, K=200 (h only): gates = GX + Whh . h(t-1).
//   Per-step launch (ordering by launch boundary). Grid-stride tiles on a
//   fixed 296-CTA grid. h double-buffered.
// ---------------------------------------------------------------------------
#define G_STEP 296
#define SMEM_STEP (MT * 51 * 16)     // 13056 B

__global__ __launch_bounds__(256, 2) void step_kernel(const int* __restrict__ lengths,
                                                      int t) {
    extern __shared__ float4 Asm4[];   // [MT][51]
    int tid = threadIdx.x;
    int mth = tid & 7;
    int kl  = tid >> 3;                // 0..31

    const float4* __restrict__ h_in = g_hA4[t & 1];
    float4* __restrict__       h_out = g_hA4[(t & 1) ^ 1];
    int cnt = g_cnt[t];
    long gxbase = g_off[t];
    int nrt = (cnt + MT - 1) / MT;
    int tiles = nrt * NKT;

    for (int tk = blockIdx.x; tk < tiles; tk += G_STEP) {
        int rt = tk % nrt;
        int kt = tk / nrt;
        int mbase = rt * MT;

        // stage h(t-1) tile
        for (int idx = tid; idx < MT * 50; idx += 256) {
            int m = idx / 50, k4 = idx % 50;
            int r = mbase + m; if (r > S - 1) r = S - 1;
            Asm4[m * 51 + k4] = h_in[r * 50 + k4];
        }
        __syncthreads();

        int kap  = kt * KT + kl;
        int kapc = (kap < H) ? kap : (H - 1);
        const float4* __restrict__ wr = &g_W4[0][kapc * K2 + H];  // Whh rows
        int r0 = mbase + mth;      int r0c = (r0 < cnt) ? r0 : (cnt - 1);
        int r1 = mbase + mth + 8;  int r1c = (r1 < cnt) ? r1 : (cnt - 1);
        float4 acc0 = g_GX4[(gxbase + r0c) * H + kapc];
        float4 acc1 = g_GX4[(gxbase + r1c) * H + kapc];

#pragma unroll 2
        for (int k4 = 0; k4 < 50; k4++) {
            float4 w0 = wr[k4 * 4 + 0];
            float4 w1 = wr[k4 * 4 + 1];
            float4 w2 = wr[k4 * 4 + 2];
            float4 w3 = wr[k4 * 4 + 3];
            float4 a0 = Asm4[mth * 51 + k4];
            float4 a1 = Asm4[(mth + 8) * 51 + k4];
            acc0.x = fmaf(w0.x, a0.x, acc0.x); acc0.y = fmaf(w0.y, a0.x, acc0.y);
            acc0.z = fmaf(w0.z, a0.x, acc0.z); acc0.w = fmaf(w0.w, a0.x, acc0.w);
            acc1.x = fmaf(w0.x, a1.x, acc1.x); acc1.y = fmaf(w0.y, a1.x, acc1.y);
            acc1.z = fmaf(w0.z, a1.x, acc1.z); acc1.w = fmaf(w0.w, a1.x, acc1.w);
            acc0.x = fmaf(w1.x, a0.y, acc0.x); acc0.y = fmaf(w1.y, a0.y, acc0.y);
            acc0.z = fmaf(w1.z, a0.y, acc0.z); acc0.w = fmaf(w1.w, a0.y, acc0.w);
            acc1.x = fmaf(w1.x, a1.y, acc1.x); acc1.y = fmaf(w1.y, a1.y, acc1.y);
            acc1.z = fmaf(w1.z, a1.y, acc1.z); acc1.w = fmaf(w1.w, a1.y, acc1.w);
            acc0.x = fmaf(w2.x, a0.z, acc0.x); acc0.y = fmaf(w2.y, a0.z, acc0.y);
            acc0.z = fmaf(w2.z, a0.z, acc0.z); acc0.w = fmaf(w2.w, a0.z, acc0.w);
            acc1.x = fmaf(w2.x, a1.z, acc1.x); acc1.y = fmaf(w2.y, a1.z, acc1.y);
            acc1.z = fmaf(w2.z, a1.z, acc1.z); acc1.w = fmaf(w2.w, a1.z, acc1.w);
            acc0.x = fmaf(w3.x, a0.w, acc0.x); acc0.y = fmaf(w3.y, a0.w, acc0.y);
            acc0.z = fmaf(w3.z, a0.w, acc0.z); acc0.w = fmaf(w3.w, a0.w, acc0.w);
            acc1.x = fmaf(w3.x, a1.w, acc1.x); acc1.y = fmaf(w3.y, a1.w, acc1.y);
            acc1.z = fmaf(w3.z, a1.w, acc1.z); acc1.w = fmaf(w3.w, a1.w, acc1.w);
        }

        if (kap < H) {
#pragma unroll
            for (int rr = 0; rr < 2; rr++) {
                float4 acc = rr ? acc1 : acc0;
                int r = mbase + mth + 8 * rr;
                if (r < cnt) {
                    float ig = sigf(acc.x);
                    float fg = sigf(acc.y);
                    float gg = tanhf(acc.z);
                    float og = sigf(acc.w);
                    int off = r * H + kap;
                    float c = fg * ((float*)g_cA4)[off] + ig * gg;
                    float h = og * tanhf(c);
                    ((float*)g_cA4)[off] = c;
                    ((float*)h_out)[off] = h;
                    int s = g_order[r];
                    if (lengths[s] == t + 1) g_emb[s * H + kap] = h;
                }
            }
        }
        __syncthreads();   // Asm4 reads done before next tile's staging
    }
}

// ---------------------------------------------------------------------------
// Kernel 6: input projections  out4[t][kap] = b4 + W_in . x(t)
// ---------------------------------------------------------------------------
__global__ void proj_kernel(const float* __restrict__ words, int x_sel, int T, int set) {
    int t = blockIdx.x;
    if (t >= T) return;
    const float* xbase;
    long xstride;
    float4* out;
    if (x_sel == 0)      { xbase = words + (long)MID * W * H; xstride =  H; out = g_GT4; }
    else if (x_sel == 1) { xbase = g_emb;                     xstride =  H; out = g_GP4; }
    else                 { xbase = g_emb + (long)(S - 1) * H; xstride = -H; out = g_GQ4; }

    __shared__ float xs[H];
    int tid = threadIdx.x;
    if (tid < H) xs[tid] = xbase[(long)t * xstride + tid];
    __syncthreads();
    if (tid >= H) return;
    int kap = tid;
    const float4* __restrict__ wr = &g_W4[set][kap * K2];
    float4 acc = g_b4[set][kap];
#pragma unroll 4
    for (int k = 0; k < H; k++) {
        float a = xs[k];
        float4 w = wr[k];
        acc.x = fmaf(w.x, a, acc.x);
        acc.y = fmaf(w.y, a, acc.y);
        acc.z = fmaf(w.z, a, acc.z);
        acc.w = fmaf(w.w, a, acc.w);
    }
    out[t * H + kap] = acc;
}

// ---------------------------------------------------------------------------
// Kernel 7: serial LSTM recurrence, 4-CTA cluster, whh slice in SMEM
// ---------------------------------------------------------------------------
#define CL 4
struct RecParams {
    int gx_sel;
    int set;
    const float* h0;
    const float* c0;
    int out_sel;
    int steps;
    const int* steps_dev;
};

#define REC_SMEM (50 * H * 16 + 256 * 4 + 64 * 4 + 4 * 50 * 16)

__device__ __forceinline__ void cluster_sync_() {
    asm volatile("barrier.cluster.arrive.aligned;" ::: "memory");
    asm volatile("barrier.cluster.wait.aligned;" ::: "memory");
}

__global__ void __cluster_dims__(CL, 1, 1) __launch_bounds__(256, 1)
rec_kernel(RecParams p0, RecParams p1, int ncl) {
    int cid = blockIdx.x / CL;
    if (cid >= ncl) return;
    RecParams P = (cid == 0) ? p0 : p1;

    const float4* gx = (P.gx_sel == 0) ? g_GT4 : (P.gx_sel == 1) ? g_GP4 : g_GQ4;
    float* out = (P.out_sel == 0) ? (g_emb + (long)MID * H)
               : (P.out_sel == 1) ? g_prevh : g_posth;
    const float4* w4 = g_W4[P.set];

    extern __shared__ float smem[];
    float4* Wsm = (float4*)smem;                       // [50][200]
    float*  h_sm = (float*)(Wsm + 50 * H);             // [200] (pad 256)
    float*  c_sm = h_sm + 256;                         // [50]  (pad 64)
    float4* psum = (float4*)(c_sm + 64);               // [4][50]

    int tid = threadIdx.x;
    int r = blockIdx.x % CL;

    for (int idx = tid; idx < 50 * H; idx += 256) {
        int kl = idx / H, k = idx % H;
        Wsm[kl * H + k] = w4[(r * 50 + kl) * K2 + H + k];
    }
    for (int k = tid; k < H; k += 256) h_sm[k] = P.h0[k];
    if (tid < 50) c_sm[tid] = P.c0[r * 50 + tid];
    int steps = P.steps_dev ? P.steps_dev[0] : P.steps;
    __syncthreads();
    cluster_sync_();

    for (int t = 0; t < steps; t++) {
        if (tid < 200) {
            int c4 = tid & 3, kl = tid >> 2;
            float4 acc = make_float4(0.f, 0.f, 0.f, 0.f);
            const float4* wrow = &Wsm[kl * H + c4 * 50];
            const float* hp = &h_sm[c4 * 50];
#pragma unroll 10
            for (int k = 0; k < 50; k++) {
                float a = hp[k];
                float4 w = wrow[k];
                acc.x = fmaf(w.x, a, acc.x);
                acc.y = fmaf(w.y, a, acc.y);
                acc.z = fmaf(w.z, a, acc.z);
                acc.w = fmaf(w.w, a, acc.w);
            }
            psum[c4 * 50 + kl] = acc;
        }
        __syncthreads();
        if (tid < 50) {
            float4 g = gx[t * H + r * 50 + tid];
            float4 a0 = psum[0 * 50 + tid], a1 = psum[1 * 50 + tid];
            float4 a2 = psum[2 * 50 + tid], a3 = psum[3 * 50 + tid];
            g.x += a0.x + a1.x + a2.x + a3.x;
            g.y += a0.y + a1.y + a2.y + a3.y;
            g.z += a0.z + a1.z + a2.z + a3.z;
            g.w += a0.w + a1.w + a2.w + a3.w;
            float ig = sigf(g.x), fg = sigf(g.y), gg = tanhf(g.z), og = sigf(g.w);
            float cn = fg * c_sm[tid] + ig * gg;
            c_sm[tid] = cn;
            float hn = og * tanhf(cn);
            int hidx = r * 50 + tid;
            uint32_t laddr = (uint32_t)__cvta_generic_to_shared(&h_sm[hidx]);
#pragma unroll
            for (int tr = 0; tr < CL; tr++) {
                uint32_t raddr;
                asm volatile("mapa.shared::cluster.u32 %0, %1, %2;"
                             : "=r"(raddr) : "r"(laddr), "r"(tr));
                asm volatile("st.shared::cluster.f32 [%0], %1;"
                             :: "r"(raddr), "f"(hn) : "memory");
            }
        }
        cluster_sync_();
    }

    if (tid < 50) out[r * 50 + tid] = h_sm[r * 50 + tid];
}

// ---------------------------------------------------------------------------
// Kernel 8: final FC
// ---------------------------------------------------------------------------
__global__ void fc_kernel(const float* __restrict__ fcw,
                          const float* __restrict__ fcb,
                          float* __restrict__ out) {
    __shared__ float feat[K2];
    int tid = threadIdx.x;
    if (tid < H) { feat[tid] = g_prevh[tid]; feat[H + tid] = g_posth[tid]; }
    __syncthreads();
    if (tid < H) {
        float acc = fcb[tid];
        const float* wr = &fcw[tid * K2];
#pragma unroll 4
        for (int k = 0; k < K2; k++) acc = fmaf(wr[k], feat[k], acc);
        out[tid] = acc;
    }
}

// ---------------------------------------------------------------------------
// Launch
// ---------------------------------------------------------------------------
extern "C" void kernel_launch(void* const* d_in, const int* in_sizes, int n_in,
                              void* d_out, int out_size) {
    const float* words   = (const float*)d_in[0];
    const int*   lengths = (const int*)  d_in[1];
    const float* h0w     = (const float*)d_in[2];
    const float* c0w     = (const float*)d_in[3];
    const float* h0p     = (const float*)d_in[4];
    const float* c0p     = (const float*)d_in[5];
    const float* h0q     = (const float*)d_in[6];
    const float* c0q     = (const float*)d_in[7];
    const float* fc_w    = (const float*)d_in[24];
    const float* fc_b    = (const float*)d_in[25];
    float* out = (float*)d_out;

    cudaFuncSetAttribute(rec_kernel, cudaFuncAttributeMaxDynamicSharedMemorySize,
                         REC_SMEM);
    cudaFuncSetAttribute(step_kernel, cudaFuncAttributeMaxDynamicSharedMemorySize,
                         SMEM_STEP);

    // 1. sort sentences by length (desc) + counts + prefix offsets
    sort_kernel<<<1, 256>>>(lengths);

    // 2. all weight reorders in ONE launch
    PrepArgs pa;
    for (int i = 0; i < 4; i++) {
        pa.wih[i] = (const float*)d_in[8 + 4 * i];
        pa.whh[i] = (const float*)d_in[9 + 4 * i];
        pa.bih[i] = (const float*)d_in[10 + 4 * i];
        pa.bhh[i] = (const float*)d_in[11 + 4 * i];
    }
    dim3 pgrid((H * K2 + 255) / 256, 4);
    prep_kernel<<<pgrid, 256>>>(pa);

    // 3. init state (buffer 0)
    init_kernel<<<(S * H + 255) / 256, 256>>>(h0w, c0w);

    // 4. GX: fully-parallel ragged input-projection GEMM (half of all work,
    //    zero serialization)
    dim3 ggrid(NKT, (S + MT - 1) / MT, W);
    gx_kernel<<<ggrid, 256>>>(words);

    // 5. phase A: 128 per-step K=200 launches (slot #5 = t0 for ncu -s 5)
    for (int t = 0; t < W; t++)
        step_kernel<<<G_STEP, 256, SMEM_STEP>>>(lengths, t);

    // 6. tgt input projection + recurrence overwrites emb[MID]
    proj_kernel<<<W, 256>>>(words, 0, W, 1);
    RecParams Ptgt;
    Ptgt.gx_sel = 0; Ptgt.set = 1;
    Ptgt.h0 = h0w + (long)MID * H; Ptgt.c0 = c0w + (long)MID * H;
    Ptgt.out_sel = 0; Ptgt.steps = 0; Ptgt.steps_dev = lengths + MID;
    rec_kernel<<<CL, 256, REC_SMEM>>>(Ptgt, Ptgt, 1);

    // 7. prev/post input projections
    proj_kernel<<<NSEQ_PREV, 256>>>(words, 1, NSEQ_PREV, 2);
    proj_kernel<<<NSEQ_PREV, 256>>>(words, 2, NSEQ_PREV, 3);

    // 8. prev + post recurrences, concurrent
    RecParams Pprev, Ppost;
    Pprev.gx_sel = 1; Pprev.set = 2; Pprev.h0 = h0p; Pprev.c0 = c0p;
    Pprev.out_sel = 1; Pprev.steps = NSEQ_PREV; Pprev.steps_dev = nullptr;
    Ppost.gx_sel = 2; Ppost.set = 3; Ppost.h0 = h0q; Ppost.c0 = c0q;
    Ppost.out_sel = 2; Ppost.steps = NSEQ_PREV; Ppost.steps_dev = nullptr;
    rec_kernel<<<2 * CL, 256, REC_SMEM>>>(Pprev, Ppost, 2);

    // 9. final FC -> d_out [200]
    fc_kernel<<<1, 256>>>(fc_w, fc_b, out);
}

// round 12
// speedup vs baseline: 1.7312x; 1.2234x over previous
#include <cuda_runtime.h>
#include <cstdint>
#include <math.h>

// Problem dimensions (fixed by the dataset)
#define H   200
#define S   1025
#define W   128
#define MID 512
#define NSEQ_PREV 513   // sentences 0..512
#define K2  (2*H)       // 400 : [x ; h]

// ---------------------------------------------------------------------------
// Device scratch (static globals: no allocation anywhere)
// ---------------------------------------------------------------------------
__device__ float4 g_W4[4][H * K2];   // gate-interleaved weights (i,f,g,o per k)
__device__ float4 g_b4[4][H];        // combined bias bih+bhh, interleaved
__device__ int    g_order[S];        // sentence indices sorted by length desc
__device__ int    g_cnt[W];          // cnt[t] = #sentences with len > t
__device__ int    g_off[W + 1];      // prefix sums of cnt (ragged GX offsets)
__device__ float  g_emb[S * H];      // sentence embeddings (original order)
// Precomputed input projection for ALL valid (t, rank) pairs, ragged layout:
// row (g_off[t] + r) holds  b + Wih . x[g_order[r]][t]  as H float4 gates.
__device__ float4 g_GX4[(size_t)S * W * H];
__device__ float4 g_GT4[W * H];          // tgt input projection
__device__ float4 g_GP4[NSEQ_PREV * H];  // prev input projection
__device__ float4 g_GQ4[NSEQ_PREV * H];  // post input projection (reversed)
__device__ float  g_prevh[H];
__device__ float  g_posth[H];

__device__ __forceinline__ float sigf(float x) { return 1.0f / (1.0f + expf(-x)); }

__device__ __forceinline__ void cluster_sync_() {
    asm volatile("barrier.cluster.arrive.aligned;" ::: "memory");
    asm volatile("barrier.cluster.wait.aligned;" ::: "memory");
}

// ---------------------------------------------------------------------------
// Kernel 1: counting sort by length (desc) + active counts + prefix offsets
// ---------------------------------------------------------------------------
__global__ void sort_kernel(const int* __restrict__ lengths) {
    __shared__ int hist[W + 1];
    __shared__ int cur[W + 1];
    int tid = threadIdx.x;
    for (int i = tid; i <= W; i += blockDim.x) hist[i] = 0;
    __syncthreads();
    for (int s = tid; s < S; s += blockDim.x) atomicAdd(&hist[lengths[s]], 1);
    __syncthreads();
    if (tid == 0) {
        int run = 0;
        for (int L = W; L >= 1; L--) { cur[L] = run; run += hist[L]; }
        int off = 0;
        for (int t = 0; t < W; t++) {
            int c = (t == 0) ? run : cur[t];
            g_cnt[t] = c;
            g_off[t] = off;
            off += c;
        }
        g_off[W] = off;
    }
    __syncthreads();
    for (int s = tid; s < S; s += blockDim.x) {
        int r = atomicAdd(&cur[lengths[s]], 1);
        g_order[r] = s;   // rank among equal lengths nondeterministic but
                          // results are permutation-invariant
    }
}

// ---------------------------------------------------------------------------
// Kernel 2: ALL four weight sets reordered in one launch (blockIdx.y = set)
// ---------------------------------------------------------------------------
struct PrepArgs {
    const float* wih[4];
    const float* whh[4];
    const float* bih[4];
    const float* bhh[4];
};
__global__ void prep_kernel(PrepArgs pa) {
    int set = blockIdx.y;
    int idx = blockIdx.x * blockDim.x + threadIdx.x;
    if (idx >= H * K2) return;
    const float* wih = pa.wih[set];
    const float* whh = pa.whh[set];
    int kap = idx / K2;
    int k   = idx % K2;
    float4 v;
    if (k < H) {
        v.x = wih[(0 * H + kap) * H + k];
        v.y = wih[(1 * H + kap) * H + k];
        v.z = wih[(2 * H + kap) * H + k];
        v.w = wih[(3 * H + kap) * H + k];
    } else {
        int kk = k - H;
        v.x = whh[(0 * H + kap) * H + kk];
        v.y = whh[(1 * H + kap) * H + kk];
        v.z = whh[(2 * H + kap) * H + kk];
        v.w = whh[(3 * H + kap) * H + kk];
    }
    g_W4[set][idx] = v;
    if (k == 0) {
        const float* bih = pa.bih[set];
        const float* bhh = pa.bhh[set];
        float4 b;
        b.x = bih[0 * H + kap] + bhh[0 * H + kap];
        b.y = bih[1 * H + kap] + bhh[1 * H + kap];
        b.z = bih[2 * H + kap] + bhh[2 * H + kap];
        b.w = bih[3 * H + kap] + bhh[3 * H + kap];
        g_b4[set][kap] = b;
    }
}

// ---------------------------------------------------------------------------
// Kernel 3: GX precompute — fully parallel ragged GEMM (no serial dep):
//   GX[g_off[t]+r][kap] = b + Wih . x[g_order[r]][t]   for r < cnt[t].
// ---------------------------------------------------------------------------
#define MT 16
#define KT 32
#define NKT 7                        // ceil(200/32)

__global__ __launch_bounds__(256) void gx_kernel(const float* __restrict__ words) {
    int t = blockIdx.z;
    int cnt = g_cnt[t];
    int mbase = blockIdx.y * MT;
    if (mbase >= cnt) return;

    __shared__ float4 Xs[MT * 51];     // [16][50] +1 pad
    int tid = threadIdx.x;
    int mth = tid & 7;
    int kl  = tid >> 3;

    for (int idx = tid; idx < MT * 50; idx += 256) {
        int m = idx / 50, k4 = idx % 50;
        int r = mbase + m; if (r > cnt - 1) r = cnt - 1;
        int s = g_order[r];
        Xs[m * 51 + k4] = ((const float4*)(words + ((long)s * W + t) * H))[k4];
    }
    __syncthreads();

    int kap  = blockIdx.x * KT + kl;
    int kapc = (kap < H) ? kap : (H - 1);
    const float4* __restrict__ wr = &g_W4[0][kapc * K2];   // Wih rows: k in [0,H)
    float4 b = g_b4[0][kapc];
    float4 acc0 = b, acc1 = b;

#pragma unroll 2
    for (int k4 = 0; k4 < 50; k4++) {
        float4 w0 = wr[k4 * 4 + 0];
        float4 w1 = wr[k4 * 4 + 1];
        float4 w2 = wr[k4 * 4 + 2];
        float4 w3 = wr[k4 * 4 + 3];
        float4 a0 = Xs[mth * 51 + k4];
        float4 a1 = Xs[(mth + 8) * 51 + k4];
        acc0.x = fmaf(w0.x, a0.x, acc0.x); acc0.y = fmaf(w0.y, a0.x, acc0.y);
        acc0.z = fmaf(w0.z, a0.x, acc0.z); acc0.w = fmaf(w0.w, a0.x, acc0.w);
        acc1.x = fmaf(w0.x, a1.x, acc1.x); acc1.y = fmaf(w0.y, a1.x, acc1.y);
        acc1.z = fmaf(w0.z, a1.x, acc1.z); acc1.w = fmaf(w0.w, a1.x, acc1.w);
        acc0.x = fmaf(w1.x, a0.y, acc0.x); acc0.y = fmaf(w1.y, a0.y, acc0.y);
        acc0.z = fmaf(w1.z, a0.y, acc0.z); acc0.w = fmaf(w1.w, a0.y, acc0.w);
        acc1.x = fmaf(w1.x, a1.y, acc1.x); acc1.y = fmaf(w1.y, a1.y, acc1.y);
        acc1.z = fmaf(w1.z, a1.y, acc1.z); acc1.w = fmaf(w1.w, a1.y, acc1.w);
        acc0.x = fmaf(w2.x, a0.z, acc0.x); acc0.y = fmaf(w2.y, a0.z, acc0.y);
        acc0.z = fmaf(w2.z, a0.z, acc0.z); acc0.w = fmaf(w2.w, a0.z, acc0.w);
        acc1.x = fmaf(w2.x, a1.z, acc1.x); acc1.y = fmaf(w2.y, a1.z, acc1.y);
        acc1.z = fmaf(w2.z, a1.z, acc1.z); acc1.w = fmaf(w2.w, a1.z, acc1.w);
        acc0.x = fmaf(w3.x, a0.w, acc0.x); acc0.y = fmaf(w3.y, a0.w, acc0.y);
        acc0.z = fmaf(w3.z, a0.w, acc0.z); acc0.w = fmaf(w3.w, a0.w, acc0.w);
        acc1.x = fmaf(w3.x, a1.w, acc1.x); acc1.y = fmaf(w3.y, a1.w, acc1.y);
        acc1.z = fmaf(w3.z, a1.w, acc1.z); acc1.w = fmaf(w3.w, a1.w, acc1.w);
    }

    if (kap < H) {
        long base = g_off[t];
#pragma unroll
        for (int rr = 0; rr < 2; rr++) {
            int r = mbase + mth + 8 * rr;
            if (r < cnt)
                g_GX4[(base + r) * H + kap] = rr ? acc1 : acc0;
        }
    }
}

// ---------------------------------------------------------------------------
// Kernel 4: WORD-LEVEL LSTM, ONE LAUNCH. Sentences are independent: rows are
//   partitioned across 33 independent 4-CTA clusters; cluster cid owns ranks
//   {cid + 33j} (interleaved over sorted order -> balanced AND per-step
//   active set is a prefix in j). Each CTA owns a 50-kappa slice with its
//   Whh slice RESIDENT in SMEM; h double-buffered in SMEM, broadcast via
//   DSMEM; one cluster_sync per time step. No grid barriers, no relaunches.
//   Per thread: 4 rows x 1 kl x 4 gates per weight load (weights 1 FMA/B).
// ---------------------------------------------------------------------------
#define NCL  33
#define CLW  4
#define RMAX 32
// Wsm [50][201] float4 + h[2][32][200] f + c[32*50] f + len/s ints
#define WL_SMEM (50 * 201 * 16 + 2 * RMAX * 200 * 4 + RMAX * 50 * 4 + RMAX * 8)

__global__ void __cluster_dims__(CLW, 1, 1) __launch_bounds__(256, 1)
wordlstm_kernel(const float* __restrict__ h0w, const float* __restrict__ c0w,
                const int* __restrict__ lengths) {
    extern __shared__ float smemf[];
    float4* Wsm   = (float4*)smemf;                    // [50][201] (pad: stride 201)
    float*  hb    = (float*)(Wsm + 50 * 201);          // [2][RMAX*200]
    float*  c_sm  = hb + 2 * RMAX * 200;               // [RMAX*50]
    int*    len_sm = (int*)(c_sm + RMAX * 50);         // [RMAX]
    int*    s_sm   = len_sm + RMAX;                    // [RMAX]

    int tid = threadIdx.x;
    int rk  = blockIdx.x % CLW;    // cta rank in cluster (kappa slice)
    int cid = blockIdx.x / CLW;    // cluster id

    // Stage Whh slice (50 kappa x 200 k, gate-interleaved float4)
    for (int idx = tid; idx < 50 * 200; idx += 256) {
        int kl = idx / 200, k = idx % 200;
        Wsm[kl * 201 + k] = g_W4[0][(rk * 50 + kl) * K2 + H + k];
    }
    // Init h (buffer 0), c, lengths, sentence ids
    for (int idx = tid; idx < RMAX * 200; idx += 256) {
        int j = idx / 200, k = idx % 200;
        int r = cid + NCL * j;
        hb[idx] = (r < S) ? h0w[g_order[r] * H + k] : 0.f;
    }
    for (int idx = tid; idx < RMAX * 50; idx += 256) {
        int j = idx / 50, kl = idx % 50;
        int r = cid + NCL * j;
        c_sm[idx] = (r < S) ? c0w[g_order[r] * H + rk * 50 + kl] : 0.f;
    }
    if (tid < RMAX) {
        int r = cid + NCL * tid;
        int s = (r < S) ? g_order[r] : 0;
        s_sm[tid] = s;
        len_sm[tid] = (r < S) ? lengths[s] : 0;
    }
    __syncthreads();
    cluster_sync_();   // peers' h buffers + weights ready before any step

    int p = 0;
    for (int t = 0; t < W; t++) {
        int cnt = g_cnt[t];
        if (cnt <= cid) break;                       // uniform per cluster
        int act = (cnt - cid + NCL - 1) / NCL;       // active rows (prefix in j)
        const float* __restrict__ hin = hb + p * (RMAX * 200);
        float* hout = hb + (p ^ 1) * (RMAX * 200);
        long gxb = g_off[t];
        int npair = ((act + 3) >> 2) * 50;           // 4 rows per weight load

        for (int idx = tid; idx < npair; idx += 256) {
            int jp = idx / 50, kl = idx % 50;
            int j0 = 4 * jp;
            int j1c = (j0 + 1 < act) ? j0 + 1 : act - 1;
            int j2c = (j0 + 2 < act) ? j0 + 2 : act - 1;
            int j3c = (j0 + 3 < act) ? j0 + 3 : act - 1;
            int kg = rk * 50 + kl;
            float4 acc0 = g_GX4[(gxb + cid + NCL * j0) * H + kg];
            float4 acc1 = g_GX4[(gxb + cid + NCL * j1c) * H + kg];
            float4 acc2 = g_GX4[(gxb + cid + NCL * j2c) * H + kg];
            float4 acc3 = g_GX4[(gxb + cid + NCL * j3c) * H + kg];
            const float4* __restrict__ wr = &Wsm[kl * 201];
            const float* h0p_ = &hin[j0 * 200];
            const float* h1p_ = &hin[j1c * 200];
            const float* h2p_ = &hin[j2c * 200];
            const float* h3p_ = &hin[j3c * 200];
#pragma unroll 2
            for (int k = 0; k < 200; k++) {
                float4 w = wr[k];
                float a0 = h0p_[k], a1 = h1p_[k], a2 = h2p_[k], a3 = h3p_[k];
                acc0.x = fmaf(w.x, a0, acc0.x); acc0.y = fmaf(w.y, a0, acc0.y);
                acc0.z = fmaf(w.z, a0, acc0.z); acc0.w = fmaf(w.w, a0, acc0.w);
                acc1.x = fmaf(w.x, a1, acc1.x); acc1.y = fmaf(w.y, a1, acc1.y);
                acc1.z = fmaf(w.z, a1, acc1.z); acc1.w = fmaf(w.w, a1, acc1.w);
                acc2.x = fmaf(w.x, a2, acc2.x); acc2.y = fmaf(w.y, a2, acc2.y);
                acc2.z = fmaf(w.z, a2, acc2.z); acc2.w = fmaf(w.w, a2, acc2.w);
                acc3.x = fmaf(w.x, a3, acc3.x); acc3.y = fmaf(w.y, a3, acc3.y);
                acc3.z = fmaf(w.z, a3, acc3.z); acc3.w = fmaf(w.w, a3, acc3.w);
            }
#pragma unroll
            for (int n = 0; n < 4; n++) {
                int j = j0 + n;
                if (j >= act) break;
                float4 acc = (n == 0) ? acc0 : (n == 1) ? acc1
                           : (n == 2) ? acc2 : acc3;
                float ig = sigf(acc.x);
                float fg = sigf(acc.y);
                float gg = tanhf(acc.z);
                float og = sigf(acc.w);
                float c = fg * c_sm[j * 50 + kl] + ig * gg;
                c_sm[j * 50 + kl] = c;
                float h = og * tanhf(c);
                // broadcast h into next-parity buffer of ALL 4 cluster CTAs
                uint32_t laddr = (uint32_t)__cvta_generic_to_shared(
                    &hout[j * 200 + kg]);
#pragma unroll
                for (int tr = 0; tr < CLW; tr++) {
                    uint32_t ra;
                    asm volatile("mapa.shared::cluster.u32 %0, %1, %2;"
                                 : "=r"(ra) : "r"(laddr), "r"(tr));
                    asm volatile("st.shared::cluster.f32 [%0], %1;"
                                 :: "r"(ra), "f"(h) : "memory");
                }
                if (len_sm[j] == t + 1)
                    g_emb[s_sm[j] * H + kg] = h;
            }
        }
        cluster_sync_();   // remote h stores visible before next step reads
        p ^= 1;
    }
}

// ---------------------------------------------------------------------------
// Kernel 5: input projections  out4[t][kap] = b4 + W_in . x(t)
// ---------------------------------------------------------------------------
__global__ void proj_kernel(const float* __restrict__ words, int x_sel, int T, int set) {
    int t = blockIdx.x;
    if (t >= T) return;
    const float* xbase;
    long xstride;
    float4* out;
    if (x_sel == 0)      { xbase = words + (long)MID * W * H; xstride =  H; out = g_GT4; }
    else if (x_sel == 1) { xbase = g_emb;                     xstride =  H; out = g_GP4; }
    else                 { xbase = g_emb + (long)(S - 1) * H; xstride = -H; out = g_GQ4; }

    __shared__ float xs[H];
    int tid = threadIdx.x;
    if (tid < H) xs[tid] = xbase[(long)t * xstride + tid];
    __syncthreads();
    if (tid >= H) return;
    int kap = tid;
    const float4* __restrict__ wr = &g_W4[set][kap * K2];
    float4 acc = g_b4[set][kap];
#pragma unroll 4
    for (int k = 0; k < H; k++) {
        float a = xs[k];
        float4 w = wr[k];
        acc.x = fmaf(w.x, a, acc.x);
        acc.y = fmaf(w.y, a, acc.y);
        acc.z = fmaf(w.z, a, acc.z);
        acc.w = fmaf(w.w, a, acc.w);
    }
    out[t * H + kap] = acc;
}

// ---------------------------------------------------------------------------
// Kernel 6: serial LSTM recurrence, 4-CTA cluster, whh slice in SMEM
// ---------------------------------------------------------------------------
#define CL 4
struct RecParams {
    int gx_sel;
    int set;
    const float* h0;
    const float* c0;
    int out_sel;
    int steps;
    const int* steps_dev;
};

#define REC_SMEM (50 * H * 16 + 256 * 4 + 64 * 4 + 4 * 50 * 16)

__global__ void __cluster_dims__(CL, 1, 1) __launch_bounds__(256, 1)
rec_kernel(RecParams p0, RecParams p1, int ncl) {
    int cid = blockIdx.x / CL;
    if (cid >= ncl) return;
    RecParams P = (cid == 0) ? p0 : p1;

    const float4* gx = (P.gx_sel == 0) ? g_GT4 : (P.gx_sel == 1) ? g_GP4 : g_GQ4;
    float* out = (P.out_sel == 0) ? (g_emb + (long)MID * H)
               : (P.out_sel == 1) ? g_prevh : g_posth;
    const float4* w4 = g_W4[P.set];

    extern __shared__ float smem[];
    float4* Wsm = (float4*)smem;                       // [50][200]
    float*  h_sm = (float*)(Wsm + 50 * H);             // [200] (pad 256)
    float*  c_sm = h_sm + 256;                         // [50]  (pad 64)
    float4* psum = (float4*)(c_sm + 64);               // [4][50]

    int tid = threadIdx.x;
    int r = blockIdx.x % CL;

    for (int idx = tid; idx < 50 * H; idx += 256) {
        int kl = idx / H, k = idx % H;
        Wsm[kl * H + k] = w4[(r * 50 + kl) * K2 + H + k];
    }
    for (int k = tid; k < H; k += 256) h_sm[k] = P.h0[k];
    if (tid < 50) c_sm[tid] = P.c0[r * 50 + tid];
    int steps = P.steps_dev ? P.steps_dev[0] : P.steps;
    __syncthreads();
    cluster_sync_();

    for (int t = 0; t < steps; t++) {
        if (tid < 200) {
            int c4 = tid & 3, kl = tid >> 2;
            float4 acc = make_float4(0.f, 0.f, 0.f, 0.f);
            const float4* wrow = &Wsm[kl * H + c4 * 50];
            const float* hp = &h_sm[c4 * 50];
#pragma unroll 10
            for (int k = 0; k < 50; k++) {
                float a = hp[k];
                float4 w = wrow[k];
                acc.x = fmaf(w.x, a, acc.x);
                acc.y = fmaf(w.y, a, acc.y);
                acc.z = fmaf(w.z, a, acc.z);
                acc.w = fmaf(w.w, a, acc.w);
            }
            psum[c4 * 50 + kl] = acc;
        }
        __syncthreads();
        if (tid < 50) {
            float4 g = gx[t * H + r * 50 + tid];
            float4 a0 = psum[0 * 50 + tid], a1 = psum[1 * 50 + tid];
            float4 a2 = psum[2 * 50 + tid], a3 = psum[3 * 50 + tid];
            g.x += a0.x + a1.x + a2.x + a3.x;
            g.y += a0.y + a1.y + a2.y + a3.y;
            g.z += a0.z + a1.z + a2.z + a3.z;
            g.w += a0.w + a1.w + a2.w + a3.w;
            float ig = sigf(g.x), fg = sigf(g.y), gg = tanhf(g.z), og = sigf(g.w);
            float cn = fg * c_sm[tid] + ig * gg;
            c_sm[tid] = cn;
            float hn = og * tanhf(cn);
            int hidx = r * 50 + tid;
            uint32_t laddr = (uint32_t)__cvta_generic_to_shared(&h_sm[hidx]);
#pragma unroll
            for (int tr = 0; tr < CL; tr++) {
                uint32_t raddr;
                asm volatile("mapa.shared::cluster.u32 %0, %1, %2;"
                             : "=r"(raddr) : "r"(laddr), "r"(tr));
                asm volatile("st.shared::cluster.f32 [%0], %1;"
                             :: "r"(raddr), "f"(hn) : "memory");
            }
        }
        cluster_sync_();
    }

    if (tid < 50) out[r * 50 + tid] = h_sm[r * 50 + tid];
}

// ---------------------------------------------------------------------------
// Kernel 7: final FC
// ---------------------------------------------------------------------------
__global__ void fc_kernel(const float* __restrict__ fcw,
                          const float* __restrict__ fcb,
                          float* __restrict__ out) {
    __shared__ float feat[K2];
    int tid = threadIdx.x;
    if (tid < H) { feat[tid] = g_prevh[tid]; feat[H + tid] = g_posth[tid]; }
    __syncthreads();
    if (tid < H) {
        float acc = fcb[tid];
        const float* wr = &fcw[tid * K2];
#pragma unroll 4
        for (int k = 0; k < K2; k++) acc = fmaf(wr[k], feat[k], acc);
        out[tid] = acc;
    }
}

// ---------------------------------------------------------------------------
// Launch
// ---------------------------------------------------------------------------
extern "C" void kernel_launch(void* const* d_in, const int* in_sizes, int n_in,
                              void* d_out, int out_size) {
    const float* words   = (const float*)d_in[0];
    const int*   lengths = (const int*)  d_in[1];
    const float* h0w     = (const float*)d_in[2];
    const float* c0w     = (const float*)d_in[3];
    const float* h0p     = (const float*)d_in[4];
    const float* c0p     = (const float*)d_in[5];
    const float* h0q     = (const float*)d_in[6];
    const float* c0q     = (const float*)d_in[7];
    const float* fc_w    = (const float*)d_in[24];
    const float* fc_b    = (const float*)d_in[25];
    float* out = (float*)d_out;

    cudaFuncSetAttribute(rec_kernel, cudaFuncAttributeMaxDynamicSharedMemorySize,
                         REC_SMEM);
    cudaFuncSetAttribute(wordlstm_kernel,
                         cudaFuncAttributeMaxDynamicSharedMemorySize, WL_SMEM);

    // 1. sort sentences by length (desc) + counts + prefix offsets
    sort_kernel<<<1, 256>>>(lengths);

    // 2. all weight reorders in ONE launch
    PrepArgs pa;
    for (int i = 0; i < 4; i++) {
        pa.wih[i] = (const float*)d_in[8 + 4 * i];
        pa.whh[i] = (const float*)d_in[9 + 4 * i];
        pa.bih[i] = (const float*)d_in[10 + 4 * i];
        pa.bhh[i] = (const float*)d_in[11 + 4 * i];
    }
    dim3 pgrid((H * K2 + 255) / 256, 4);
    prep_kernel<<<pgrid, 256>>>(pa);

    // 3. GX: fully-parallel ragged input-projection GEMM
    dim3 ggrid(NKT, (S + MT - 1) / MT, W);
    gx_kernel<<<ggrid, 256>>>(words);

    // 4. WORD LSTM: one launch, 33 independent 4-CTA clusters, Whh in SMEM
    //    (launch index 3 -> ncu capture lands here)
    wordlstm_kernel<<<NCL * CLW, 256, WL_SMEM>>>(h0w, c0w, lengths);

    // 5. tgt input projection + recurrence overwrites emb[MID]
    proj_kernel<<<W, 256>>>(words, 0, W, 1);
    RecParams Ptgt;
    Ptgt.gx_sel = 0; Ptgt.set = 1;
    Ptgt.h0 = h0w + (long)MID * H; Ptgt.c0 = c0w + (long)MID * H;
    Ptgt.out_sel = 0; Ptgt.steps = 0; Ptgt.steps_dev = lengths + MID;
    rec_kernel<<<CL, 256, REC_SMEM>>>(Ptgt, Ptgt, 1);

    // 6. prev/post input projections
    proj_kernel<<<NSEQ_PREV, 256>>>(words, 1, NSEQ_PREV, 2);
    proj_kernel<<<NSEQ_PREV, 256>>>(words, 2, NSEQ_PREV, 3);

    // 7. prev + post recurrences, concurrent
    RecParams Pprev, Ppost;
    Pprev.gx_sel = 1; Pprev.set = 2; Pprev.h0 = h0p; Pprev.c0 = c0p;
    Pprev.out_sel = 1; Pprev.steps = NSEQ_PREV; Pprev.steps_dev = nullptr;
    Ppost.gx_sel = 2; Ppost.set = 3; Ppost.h0 = h0q; Ppost.c0 = c0q;
    Ppost.out_sel = 2; Ppost.steps = NSEQ_PREV; Ppost.steps_dev = nullptr;
    rec_kernel<<<2 * CL, 256, REC_SMEM>>>(Pprev, Ppost, 2);

    // 8. final FC -> d_out [200]
    fc_kernel<<<1, 256>>>(fc_w, fc_b, out);
}

// round 16
// speedup vs baseline: 1.7737x; 1.0245x over previous
#include <cuda_runtime.h>
#include <cstdint>
#include <math.h>

// Problem dimensions (fixed by the dataset)
#define H   200
#define S   1025
#define W   128
#define MID 512
#define NSEQ_PREV 513   // sentences 0..512
#define K2  (2*H)       // 400 : [x ; h]

// ---------------------------------------------------------------------------
// Device scratch (static globals: no allocation anywhere)
// ---------------------------------------------------------------------------
__device__ float4 g_W4[4][H * K2];   // gate-interleaved weights (i,f,g,o per k)
__device__ float4 g_b4[4][H];        // combined bias bih+bhh, interleaved
__device__ int    g_order[S];        // sentence indices sorted by length desc
__device__ int    g_cnt[W];          // cnt[t] = #sentences with len > t
__device__ int    g_off[W + 1];      // prefix sums of cnt (ragged GX offsets)
__device__ float  g_emb[S * H];      // sentence embeddings (original order)
// Precomputed input projection for ALL valid (t, rank) pairs, ragged layout:
// row (g_off[t] + r) holds  b + Wih . x[g_order[r]][t]  as H float4 gates.
__device__ float4 g_GX4[(size_t)S * W * H];
__device__ float4 g_GT4[W * H];          // tgt input projection
__device__ float4 g_GP4[NSEQ_PREV * H];  // prev input projection
__device__ float4 g_GQ4[NSEQ_PREV * H];  // post input projection (reversed)
__device__ float  g_prevh[H];
__device__ float  g_posth[H];

__device__ __forceinline__ float sigf(float x) { return 1.0f / (1.0f + expf(-x)); }

__device__ __forceinline__ void cluster_sync_() {
    asm volatile("barrier.cluster.arrive.aligned;" ::: "memory");
    asm volatile("barrier.cluster.wait.aligned;" ::: "memory");
}

// ---------------------------------------------------------------------------
// Kernel 1: counting sort by length (desc) + active counts + prefix offsets
// ---------------------------------------------------------------------------
__global__ void sort_kernel(const int* __restrict__ lengths) {
    __shared__ int hist[W + 1];
    __shared__ int cur[W + 1];
    int tid = threadIdx.x;
    for (int i = tid; i <= W; i += blockDim.x) hist[i] = 0;
    __syncthreads();
    for (int s = tid; s < S; s += blockDim.x) atomicAdd(&hist[lengths[s]], 1);
    __syncthreads();
    if (tid == 0) {
        int run = 0;
        for (int L = W; L >= 1; L--) { cur[L] = run; run += hist[L]; }
        int off = 0;
        for (int t = 0; t < W; t++) {
            int c = (t == 0) ? run : cur[t];
            g_cnt[t] = c;
            g_off[t] = off;
            off += c;
        }
        g_off[W] = off;
    }
    __syncthreads();
    for (int s = tid; s < S; s += blockDim.x) {
        int r = atomicAdd(&cur[lengths[s]], 1);
        g_order[r] = s;   // rank among equal lengths nondeterministic but
                          // results are permutation-invariant
    }
}

// ---------------------------------------------------------------------------
// Kernel 2: ALL four weight sets reordered in one launch (blockIdx.y = set)
// ---------------------------------------------------------------------------
struct PrepArgs {
    const float* wih[4];
    const float* whh[4];
    const float* bih[4];
    const float* bhh[4];
};
__global__ void prep_kernel(PrepArgs pa) {
    int set = blockIdx.y;
    int idx = blockIdx.x * blockDim.x + threadIdx.x;
    if (idx >= H * K2) return;
    const float* wih = pa.wih[set];
    const float* whh = pa.whh[set];
    int kap = idx / K2;
    int k   = idx % K2;
    float4 v;
    if (k < H) {
        v.x = wih[(0 * H + kap) * H + k];
        v.y = wih[(1 * H + kap) * H + k];
        v.z = wih[(2 * H + kap) * H + k];
        v.w = wih[(3 * H + kap) * H + k];
    } else {
        int kk = k - H;
        v.x = whh[(0 * H + kap) * H + kk];
        v.y = whh[(1 * H + kap) * H + kk];
        v.z = whh[(2 * H + kap) * H + kk];
        v.w = whh[(3 * H + kap) * H + kk];
    }
    g_W4[set][idx] = v;
    if (k == 0) {
        const float* bih = pa.bih[set];
        const float* bhh = pa.bhh[set];
        float4 b;
        b.x = bih[0 * H + kap] + bhh[0 * H + kap];
        b.y = bih[1 * H + kap] + bhh[1 * H + kap];
        b.z = bih[2 * H + kap] + bhh[2 * H + kap];
        b.w = bih[3 * H + kap] + bhh[3 * H + kap];
        g_b4[set][kap] = b;
    }
}

// ---------------------------------------------------------------------------
// Kernel 3: GX precompute — fully parallel ragged GEMM (no serial dep):
//   GX[g_off[t]+r][kap] = b + Wih . x[g_order[r]][t]   for r < cnt[t].
//   Tile 32 rows x 32 kappa; 4 rows/thread -> 64 FMA per 4 LDG + 4 LDS.
// ---------------------------------------------------------------------------
#define GMT 32
#define KT 32
#define NKT 7                        // ceil(200/32)

__global__ __launch_bounds__(256) void gx_kernel(const float* __restrict__ words) {
    int t = blockIdx.z;
    int cnt = g_cnt[t];
    int mbase = blockIdx.y * GMT;
    if (mbase >= cnt) return;

    __shared__ float4 Xs[GMT * 51];    // [32][50] +1 pad
    int tid = threadIdx.x;
    int mth = tid & 7;
    int kl  = tid >> 3;

    for (int idx = tid; idx < GMT * 50; idx += 256) {
        int m = idx / 50, k4 = idx % 50;
        int r = mbase + m; if (r > cnt - 1) r = cnt - 1;
        int s = g_order[r];
        Xs[m * 51 + k4] = ((const float4*)(words + ((long)s * W + t) * H))[k4];
    }
    __syncthreads();

    int kap  = blockIdx.x * KT + kl;
    int kapc = (kap < H) ? kap : (H - 1);
    const float4* __restrict__ wr = &g_W4[0][kapc * K2];   // Wih rows: k in [0,H)
    float4 b = g_b4[0][kapc];
    float4 acc[4];
#pragma unroll
    for (int rr = 0; rr < 4; rr++) acc[rr] = b;

#pragma unroll 2
    for (int k4 = 0; k4 < 50; k4++) {
        float4 w0 = wr[k4 * 4 + 0];
        float4 w1 = wr[k4 * 4 + 1];
        float4 w2 = wr[k4 * 4 + 2];
        float4 w3 = wr[k4 * 4 + 3];
#pragma unroll
        for (int rr = 0; rr < 4; rr++) {
            float4 a = Xs[(mth + 8 * rr) * 51 + k4];
            acc[rr].x = fmaf(w0.x, a.x, acc[rr].x);
            acc[rr].y = fmaf(w0.y, a.x, acc[rr].y);
            acc[rr].z = fmaf(w0.z, a.x, acc[rr].z);
            acc[rr].w = fmaf(w0.w, a.x, acc[rr].w);
            acc[rr].x = fmaf(w1.x, a.y, acc[rr].x);
            acc[rr].y = fmaf(w1.y, a.y, acc[rr].y);
            acc[rr].z = fmaf(w1.z, a.y, acc[rr].z);
            acc[rr].w = fmaf(w1.w, a.y, acc[rr].w);
            acc[rr].x = fmaf(w2.x, a.z, acc[rr].x);
            acc[rr].y = fmaf(w2.y, a.z, acc[rr].y);
            acc[rr].z = fmaf(w2.z, a.z, acc[rr].z);
            acc[rr].w = fmaf(w2.w, a.z, acc[rr].w);
            acc[rr].x = fmaf(w3.x, a.w, acc[rr].x);
            acc[rr].y = fmaf(w3.y, a.w, acc[rr].y);
            acc[rr].z = fmaf(w3.z, a.w, acc[rr].z);
            acc[rr].w = fmaf(w3.w, a.w, acc[rr].w);
        }
    }

    if (kap < H) {
        long base = g_off[t];
#pragma unroll
        for (int rr = 0; rr < 4; rr++) {
            int r = mbase + mth + 8 * rr;
            if (r < cnt)
                g_GX4[(base + r) * H + kap] = acc[rr];
        }
    }
}

// ---------------------------------------------------------------------------
// Kernel 4: WORD-LEVEL LSTM, ONE LAUNCH. 33 independent 4-CTA clusters,
//   cluster cid owns ranks {cid + 33j}. Whh slice resident in SMEM; h
//   double-buffered, broadcast via DSMEM; one cluster_sync per step.
//   8 rows per weight load: 1 LDS.128 (w) + 8 LDS.32 (h) -> 32 FMAs.
// ---------------------------------------------------------------------------
#define NCL  33
#define CLW  4
#define RMAX 32
#define RW   8
// Wsm [50][201] float4 + h[2][32][200] f + c[32*50] f + len/s ints
#define WL_SMEM (50 * 201 * 16 + 2 * RMAX * 200 * 4 + RMAX * 50 * 4 + RMAX * 8)

__global__ void __cluster_dims__(CLW, 1, 1) __launch_bounds__(256, 1)
wordlstm_kernel(const float* __restrict__ h0w, const float* __restrict__ c0w,
                const int* __restrict__ lengths) {
    extern __shared__ float smemf[];
    float4* Wsm   = (float4*)smemf;                    // [50][201] (pad: stride 201)
    float*  hb    = (float*)(Wsm + 50 * 201);          // [2][RMAX*200]
    float*  c_sm  = hb + 2 * RMAX * 200;               // [RMAX*50]
    int*    len_sm = (int*)(c_sm + RMAX * 50);         // [RMAX]
    int*    s_sm   = len_sm + RMAX;                    // [RMAX]

    int tid = threadIdx.x;
    int rk  = blockIdx.x % CLW;    // cta rank in cluster (kappa slice)
    int cid = blockIdx.x / CLW;    // cluster id

    // Stage Whh slice (50 kappa x 200 k, gate-interleaved float4)
    for (int idx = tid; idx < 50 * 200; idx += 256) {
        int kl = idx / 200, k = idx % 200;
        Wsm[kl * 201 + k] = g_W4[0][(rk * 50 + kl) * K2 + H + k];
    }
    // Init h (buffer 0), c, lengths, sentence ids
    for (int idx = tid; idx < RMAX * 200; idx += 256) {
        int j = idx / 200, k = idx % 200;
        int r = cid + NCL * j;
        hb[idx] = (r < S) ? h0w[g_order[r] * H + k] : 0.f;
    }
    for (int idx = tid; idx < RMAX * 50; idx += 256) {
        int j = idx / 50, kl = idx % 50;
        int r = cid + NCL * j;
        c_sm[idx] = (r < S) ? c0w[g_order[r] * H + rk * 50 + kl] : 0.f;
    }
    if (tid < RMAX) {
        int r = cid + NCL * tid;
        int s = (r < S) ? g_order[r] : 0;
        s_sm[tid] = s;
        len_sm[tid] = (r < S) ? lengths[s] : 0;
    }
    __syncthreads();
    cluster_sync_();   // peers' h buffers + weights ready before any step

    int p = 0;
    for (int t = 0; t < W; t++) {
        int cnt = g_cnt[t];
        if (cnt <= cid) break;                       // uniform per cluster
        int act = (cnt - cid + NCL - 1) / NCL;       // active rows (prefix in j)
        const float* __restrict__ hin = hb + p * (RMAX * 200);
        float* hout = hb + (p ^ 1) * (RMAX * 200);
        long gxb = g_off[t];
        int npair = ((act + RW - 1) / RW) * 50;      // RW rows per weight load

        for (int idx = tid; idx < npair; idx += 256) {
            int jp = idx / 50, kl = idx % 50;
            int j0 = RW * jp;
            int kg = rk * 50 + kl;
            int jc[RW];
            float4 acc[RW];
            const float* hp[RW];
#pragma unroll
            for (int n = 0; n < RW; n++) {
                jc[n] = (j0 + n < act) ? j0 + n : act - 1;
                acc[n] = g_GX4[(gxb + cid + NCL * jc[n]) * H + kg];
                hp[n] = &hin[jc[n] * 200];
            }
            const float4* __restrict__ wr = &Wsm[kl * 201];
#pragma unroll 2
            for (int k = 0; k < 200; k++) {
                float4 w = wr[k];
#pragma unroll
                for (int n = 0; n < RW; n++) {
                    float a = hp[n][k];
                    acc[n].x = fmaf(w.x, a, acc[n].x);
                    acc[n].y = fmaf(w.y, a, acc[n].y);
                    acc[n].z = fmaf(w.z, a, acc[n].z);
                    acc[n].w = fmaf(w.w, a, acc[n].w);
                }
            }
#pragma unroll
            for (int n = 0; n < RW; n++) {
                int j = j0 + n;
                if (j >= act) break;
                float ig = sigf(acc[n].x);
                float fg = sigf(acc[n].y);
                float gg = tanhf(acc[n].z);
                float og = sigf(acc[n].w);
                float c = fg * c_sm[j * 50 + kl] + ig * gg;
                c_sm[j * 50 + kl] = c;
                float h = og * tanhf(c);
                // broadcast h into next-parity buffer of ALL 4 cluster CTAs
                uint32_t laddr = (uint32_t)__cvta_generic_to_shared(
                    &hout[j * 200 + kg]);
#pragma unroll
                for (int tr = 0; tr < CLW; tr++) {
                    uint32_t ra;
                    asm volatile("mapa.shared::cluster.u32 %0, %1, %2;"
                                 : "=r"(ra) : "r"(laddr), "r"(tr));
                    asm volatile("st.shared::cluster.f32 [%0], %1;"
                                 :: "r"(ra), "f"(h) : "memory");
                }
                if (len_sm[j] == t + 1)
                    g_emb[s_sm[j] * H + kg] = h;
            }
        }
        cluster_sync_();   // remote h stores visible before next step reads
        p ^= 1;
    }
}

// ---------------------------------------------------------------------------
// Kernel 5: input projections  out4[t][kap] = b4 + W_in . x(t)
// ---------------------------------------------------------------------------
__global__ void proj_kernel(const float* __restrict__ words, int x_sel, int T, int set) {
    int t = blockIdx.x;
    if (t >= T) return;
    const float* xbase;
    long xstride;
    float4* out;
    if (x_sel == 0)      { xbase = words + (long)MID * W * H; xstride =  H; out = g_GT4; }
    else if (x_sel == 1) { xbase = g_emb;                     xstride =  H; out = g_GP4; }
    else                 { xbase = g_emb + (long)(S - 1) * H; xstride = -H; out = g_GQ4; }

    __shared__ float xs[H];
    int tid = threadIdx.x;
    if (tid < H) xs[tid] = xbase[(long)t * xstride + tid];
    __syncthreads();
    if (tid >= H) return;
    int kap = tid;
    const float4* __restrict__ wr = &g_W4[set][kap * K2];
    float4 acc = g_b4[set][kap];
#pragma unroll 4
    for (int k = 0; k < H; k++) {
        float a = xs[k];
        float4 w = wr[k];
        acc.x = fmaf(w.x, a, acc.x);
        acc.y = fmaf(w.y, a, acc.y);
        acc.z = fmaf(w.z, a, acc.z);
        acc.w = fmaf(w.w, a, acc.w);
    }
    out[t * H + kap] = acc;
}

// ---------------------------------------------------------------------------
// Kernel 6: serial LSTM recurrence, 4-CTA cluster, whh slice in SMEM
// ---------------------------------------------------------------------------
#define CL 4
struct RecParams {
    int gx_sel;
    int set;
    const float* h0;
    const float* c0;
    int out_sel;
    int steps;
    const int* steps_dev;
};

#define REC_SMEM (50 * H * 16 + 256 * 4 + 64 * 4 + 4 * 50 * 16)

__global__ void __cluster_dims__(CL, 1, 1) __launch_bounds__(256, 1)
rec_kernel(RecParams p0, RecParams p1, int ncl) {
    int cid = blockIdx.x / CL;
    if (cid >= ncl) return;
    RecParams P = (cid == 0) ? p0 : p1;

    const float4* gx = (P.gx_sel == 0) ? g_GT4 : (P.gx_sel == 1) ? g_GP4 : g_GQ4;
    float* out = (P.out_sel == 0) ? (g_emb + (long)MID * H)
               : (P.out_sel == 1) ? g_prevh : g_posth;
    const float4* w4 = g_W4[P.set];

    extern __shared__ float smem[];
    float4* Wsm = (float4*)smem;                       // [50][200]
    float*  h_sm = (float*)(Wsm + 50 * H);             // [200] (pad 256)
    float*  c_sm = h_sm + 256;                         // [50]  (pad 64)
    float4* psum = (float4*)(c_sm + 64);               // [4][50]

    int tid = threadIdx.x;
    int r = blockIdx.x % CL;

    for (int idx = tid; idx < 50 * H; idx += 256) {
        int kl = idx / H, k = idx % H;
        Wsm[kl * H + k] = w4[(r * 50 + kl) * K2 + H + k];
    }
    for (int k = tid; k < H; k += 256) h_sm[k] = P.h0[k];
    if (tid < 50) c_sm[tid] = P.c0[r * 50 + tid];
    int steps = P.steps_dev ? P.steps_dev[0] : P.steps;
    __syncthreads();
    cluster_sync_();

    for (int t = 0; t < steps; t++) {
        if (tid < 200) {
            int c4 = tid & 3, kl = tid >> 2;
            float4 acc = make_float4(0.f, 0.f, 0.f, 0.f);
            const float4* wrow = &Wsm[kl * H + c4 * 50];
            const float* hp = &h_sm[c4 * 50];
#pragma unroll 10
            for (int k = 0; k < 50; k++) {
                float a = hp[k];
                float4 w = wrow[k];
                acc.x = fmaf(w.x, a, acc.x);
                acc.y = fmaf(w.y, a, acc.y);
                acc.z = fmaf(w.z, a, acc.z);
                acc.w = fmaf(w.w, a, acc.w);
            }
            psum[c4 * 50 + kl] = acc;
        }
        __syncthreads();
        if (tid < 50) {
            float4 g = gx[t * H + r * 50 + tid];
            float4 a0 = psum[0 * 50 + tid], a1 = psum[1 * 50 + tid];
            float4 a2 = psum[2 * 50 + tid], a3 = psum[3 * 50 + tid];
            g.x += a0.x + a1.x + a2.x + a3.x;
            g.y += a0.y + a1.y + a2.y + a3.y;
            g.z += a0.z + a1.z + a2.z + a3.z;
            g.w += a0.w + a1.w + a2.w + a3.w;
            float ig = sigf(g.x), fg = sigf(g.y), gg = tanhf(g.z), og = sigf(g.w);
            float cn = fg * c_sm[tid] + ig * gg;
            c_sm[tid] = cn;
            float hn = og * tanhf(cn);
            int hidx = r * 50 + tid;
            uint32_t laddr = (uint32_t)__cvta_generic_to_shared(&h_sm[hidx]);
#pragma unroll
            for (int tr = 0; tr < CL; tr++) {
                uint32_t raddr;
                asm volatile("mapa.shared::cluster.u32 %0, %1, %2;"
                             : "=r"(raddr) : "r"(laddr), "r"(tr));
                asm volatile("st.shared::cluster.f32 [%0], %1;"
                             :: "r"(raddr), "f"(hn) : "memory");
            }
        }
        cluster_sync_();
    }

    if (tid < 50) out[r * 50 + tid] = h_sm[r * 50 + tid];
}

// ---------------------------------------------------------------------------
// Kernel 7: final FC
// ---------------------------------------------------------------------------
__global__ void fc_kernel(const float* __restrict__ fcw,
                          const float* __restrict__ fcb,
                          float* __restrict__ out) {
    __shared__ float feat[K2];
    int tid = threadIdx.x;
    if (tid < H) { feat[tid] = g_prevh[tid]; feat[H + tid] = g_posth[tid]; }
    __syncthreads();
    if (tid < H) {
        float acc = fcb[tid];
        const float* wr = &fcw[tid * K2];
#pragma unroll 4
        for (int k = 0; k < K2; k++) acc = fmaf(wr[k], feat[k], acc);
        out[tid] = acc;
    }
}

// ---------------------------------------------------------------------------
// Launch
// ---------------------------------------------------------------------------
extern "C" void kernel_launch(void* const* d_in, const int* in_sizes, int n_in,
                              void* d_out, int out_size) {
    const float* words   = (const float*)d_in[0];
    const int*   lengths = (const int*)  d_in[1];
    const float* h0w     = (const float*)d_in[2];
    const float* c0w     = (const float*)d_in[3];
    const float* h0p     = (const float*)d_in[4];
    const float* c0p     = (const float*)d_in[5];
    const float* h0q     = (const float*)d_in[6];
    const float* c0q     = (const float*)d_in[7];
    const float* fc_w    = (const float*)d_in[24];
    const float* fc_b    = (const float*)d_in[25];
    float* out = (float*)d_out;

    cudaFuncSetAttribute(rec_kernel, cudaFuncAttributeMaxDynamicSharedMemorySize,
                         REC_SMEM);
    cudaFuncSetAttribute(wordlstm_kernel,
                         cudaFuncAttributeMaxDynamicSharedMemorySize, WL_SMEM);

    // 1. sort sentences by length (desc) + counts + prefix offsets
    sort_kernel<<<1, 256>>>(lengths);

    // 2. all weight reorders in ONE launch
    PrepArgs pa;
    for (int i = 0; i < 4; i++) {
        pa.wih[i] = (const float*)d_in[8 + 4 * i];
        pa.whh[i] = (const float*)d_in[9 + 4 * i];
        pa.bih[i] = (const float*)d_in[10 + 4 * i];
        pa.bhh[i] = (const float*)d_in[11 + 4 * i];
    }
    dim3 pgrid((H * K2 + 255) / 256, 4);
    prep_kernel<<<pgrid, 256>>>(pa);

    // 3. GX: fully-parallel ragged input-projection GEMM (32-row tiles)
    dim3 ggrid(NKT, (S + GMT - 1) / GMT, W);
    gx_kernel<<<ggrid, 256>>>(words);

    // 4. WORD LSTM: one launch, 33 independent 4-CTA clusters, Whh in SMEM
    wordlstm_kernel<<<NCL * CLW, 256, WL_SMEM>>>(h0w, c0w, lengths);

    // 5. tgt input projection + recurrence overwrites emb[MID]
    proj_kernel<<<W, 256>>>(words, 0, W, 1);
    RecParams Ptgt;
    Ptgt.gx_sel = 0; Ptgt.set = 1;
    Ptgt.h0 = h0w + (long)MID * H; Ptgt.c0 = c0w + (long)MID * H;
    Ptgt.out_sel = 0; Ptgt.steps = 0; Ptgt.steps_dev = lengths + MID;
    rec_kernel<<<CL, 256, REC_SMEM>>>(Ptgt, Ptgt, 1);

    // 6. prev/post input projections
    proj_kernel<<<NSEQ_PREV, 256>>>(words, 1, NSEQ_PREV, 2);
    proj_kernel<<<NSEQ_PREV, 256>>>(words, 2, NSEQ_PREV, 3);

    // 7. prev + post recurrences, concurrent
    RecParams Pprev, Ppost;
    Pprev.gx_sel = 1; Pprev.set = 2; Pprev.h0 = h0p; Pprev.c0 = c0p;
    Pprev.out_sel = 1; Pprev.steps = NSEQ_PREV; Pprev.steps_dev = nullptr;
    Ppost.gx_sel = 2; Ppost.set = 3; Ppost.h0 = h0q; Ppost.c0 = c0q;
    Ppost.out_sel = 2; Ppost.steps = NSEQ_PREV; Ppost.steps_dev = nullptr;
    rec_kernel<<<2 * CL, 256, REC_SMEM>>>(Pprev, Ppost, 2);

    // 8. final FC -> d_out [200]
    fc_kernel<<<1, 256>>>(fc_w, fc_b, out);
}

// round 17
// speedup vs baseline: 2.0786x; 1.1719x over previous
#include <cuda_runtime.h>
#include <cstdint>
#include <math.h>

// Problem dimensions (fixed by the dataset)
#define H   200
#define S   1025
#define W   128
#define MID 512
#define NSEQ_PREV 513   // sentences 0..512
#define K2  (2*H)       // 400 : [x ; h]

// ---------------------------------------------------------------------------
// Device scratch (static globals: no allocation anywhere)
// ---------------------------------------------------------------------------
__device__ float4 g_W4[4][H * K2];   // gate-interleaved weights (i,f,g,o per k)
__device__ float4 g_b4[4][H];        // combined bias bih+bhh, interleaved
__device__ int    g_order[S];        // sentence indices sorted by length desc
__device__ int    g_cnt[W];          // cnt[t] = #sentences with len > t
__device__ int    g_off[W + 1];      // prefix sums of cnt (ragged GX offsets)
__device__ float  g_emb[S * H];      // sentence embeddings (original order)
// Precomputed input projection for ALL valid (t, rank) pairs, ragged layout:
// row (g_off[t] + r) holds  b + Wih . x[g_order[r]][t]  as H float4 gates.
__device__ float4 g_GX4[(size_t)S * W * H];
__device__ float4 g_GT4[W * H];          // tgt input projection
__device__ float4 g_GP4[NSEQ_PREV * H];  // prev input projection
__device__ float4 g_GQ4[NSEQ_PREV * H];  // post input projection (reversed)
__device__ float  g_prevh[H];
__device__ float  g_posth[H];

__device__ __forceinline__ float sigf(float x) { return 1.0f / (1.0f + expf(-x)); }

__device__ __forceinline__ void cluster_sync_() {
    asm volatile("barrier.cluster.arrive.aligned;" ::: "memory");
    asm volatile("barrier.cluster.wait.aligned;" ::: "memory");
}

// ---------------------------------------------------------------------------
// Kernel 1: counting sort by length (desc) + active counts + prefix offsets
// ---------------------------------------------------------------------------
__global__ void sort_kernel(const int* __restrict__ lengths) {
    __shared__ int hist[W + 1];
    __shared__ int cur[W + 1];
    int tid = threadIdx.x;
    for (int i = tid; i <= W; i += blockDim.x) hist[i] = 0;
    __syncthreads();
    for (int s = tid; s < S; s += blockDim.x) atomicAdd(&hist[lengths[s]], 1);
    __syncthreads();
    if (tid == 0) {
        int run = 0;
        for (int L = W; L >= 1; L--) { cur[L] = run; run += hist[L]; }
        int off = 0;
        for (int t = 0; t < W; t++) {
            int c = (t == 0) ? run : cur[t];
            g_cnt[t] = c;
            g_off[t] = off;
            off += c;
        }
        g_off[W] = off;
    }
    __syncthreads();
    for (int s = tid; s < S; s += blockDim.x) {
        int r = atomicAdd(&cur[lengths[s]], 1);
        g_order[r] = s;   // rank among equal lengths nondeterministic but
                          // results are permutation-invariant
    }
}

// ---------------------------------------------------------------------------
// Kernel 2: ALL four weight sets reordered in one launch (blockIdx.y = set)
// ---------------------------------------------------------------------------
struct PrepArgs {
    const float* wih[4];
    const float* whh[4];
    const float* bih[4];
    const float* bhh[4];
};
__global__ void prep_kernel(PrepArgs pa) {
    int set = blockIdx.y;
    int idx = blockIdx.x * blockDim.x + threadIdx.x;
    if (idx >= H * K2) return;
    const float* wih = pa.wih[set];
    const float* whh = pa.whh[set];
    int kap = idx / K2;
    int k   = idx % K2;
    float4 v;
    if (k < H) {
        v.x = wih[(0 * H + kap) * H + k];
        v.y = wih[(1 * H + kap) * H + k];
        v.z = wih[(2 * H + kap) * H + k];
        v.w = wih[(3 * H + kap) * H + k];
    } else {
        int kk = k - H;
        v.x = whh[(0 * H + kap) * H + kk];
        v.y = whh[(1 * H + kap) * H + kk];
        v.z = whh[(2 * H + kap) * H + kk];
        v.w = whh[(3 * H + kap) * H + kk];
    }
    g_W4[set][idx] = v;
    if (k == 0) {
        const float* bih = pa.bih[set];
        const float* bhh = pa.bhh[set];
        float4 b;
        b.x = bih[0 * H + kap] + bhh[0 * H + kap];
        b.y = bih[1 * H + kap] + bhh[1 * H + kap];
        b.z = bih[2 * H + kap] + bhh[2 * H + kap];
        b.w = bih[3 * H + kap] + bhh[3 * H + kap];
        g_b4[set][kap] = b;
    }
}

// ---------------------------------------------------------------------------
// Kernel 3: GX precompute — fully parallel ragged GEMM (no serial dep):
//   GX[g_off[t]+r][kap] = b + Wih . x[g_order[r]][t]   for r < cnt[t].
//   Tile 32 rows x 32 kappa; 4 rows/thread -> 64 FMA per 4 LDG + 4 LDS.
// ---------------------------------------------------------------------------
#define GMT 32
#define KT 32
#define NKT 7                        // ceil(200/32)

__global__ __launch_bounds__(256) void gx_kernel(const float* __restrict__ words) {
    int t = blockIdx.z;
    int cnt = g_cnt[t];
    int mbase = blockIdx.y * GMT;
    if (mbase >= cnt) return;

    __shared__ float4 Xs[GMT * 51];    // [32][50] +1 pad
    int tid = threadIdx.x;
    int mth = tid & 7;
    int kl  = tid >> 3;

    for (int idx = tid; idx < GMT * 50; idx += 256) {
        int m = idx / 50, k4 = idx % 50;
        int r = mbase + m; if (r > cnt - 1) r = cnt - 1;
        int s = g_order[r];
        Xs[m * 51 + k4] = ((const float4*)(words + ((long)s * W + t) * H))[k4];
    }
    __syncthreads();

    int kap  = blockIdx.x * KT + kl;
    int kapc = (kap < H) ? kap : (H - 1);
    const float4* __restrict__ wr = &g_W4[0][kapc * K2];   // Wih rows: k in [0,H)
    float4 b = g_b4[0][kapc];
    float4 acc[4];
#pragma unroll
    for (int rr = 0; rr < 4; rr++) acc[rr] = b;

#pragma unroll 2
    for (int k4 = 0; k4 < 50; k4++) {
        float4 w0 = wr[k4 * 4 + 0];
        float4 w1 = wr[k4 * 4 + 1];
        float4 w2 = wr[k4 * 4 + 2];
        float4 w3 = wr[k4 * 4 + 3];
#pragma unroll
        for (int rr = 0; rr < 4; rr++) {
            float4 a = Xs[(mth + 8 * rr) * 51 + k4];
            acc[rr].x = fmaf(w0.x, a.x, acc[rr].x);
            acc[rr].y = fmaf(w0.y, a.x, acc[rr].y);
            acc[rr].z = fmaf(w0.z, a.x, acc[rr].z);
            acc[rr].w = fmaf(w0.w, a.x, acc[rr].w);
            acc[rr].x = fmaf(w1.x, a.y, acc[rr].x);
            acc[rr].y = fmaf(w1.y, a.y, acc[rr].y);
            acc[rr].z = fmaf(w1.z, a.y, acc[rr].z);
            acc[rr].w = fmaf(w1.w, a.y, acc[rr].w);
            acc[rr].x = fmaf(w2.x, a.z, acc[rr].x);
            acc[rr].y = fmaf(w2.y, a.z, acc[rr].y);
            acc[rr].z = fmaf(w2.z, a.z, acc[rr].z);
            acc[rr].w = fmaf(w2.w, a.z, acc[rr].w);
            acc[rr].x = fmaf(w3.x, a.w, acc[rr].x);
            acc[rr].y = fmaf(w3.y, a.w, acc[rr].y);
            acc[rr].z = fmaf(w3.z, a.w, acc[rr].z);
            acc[rr].w = fmaf(w3.w, a.w, acc[rr].w);
        }
    }

    if (kap < H) {
        long base = g_off[t];
#pragma unroll
        for (int rr = 0; rr < 4; rr++) {
            int r = mbase + mth + 8 * rr;
            if (r < cnt)
                g_GX4[(base + r) * H + kap] = acc[rr];
        }
    }
}

// ---------------------------------------------------------------------------
// Kernel 4: WORD-LEVEL LSTM, ONE LAUNCH. 33 independent 4-CTA clusters,
//   cluster cid owns ranks {cid + 33j}. Whh slice resident in SMEM; h
//   double-buffered, broadcast via DSMEM; one cluster_sync per step.
//   512 threads, RW=4 rows/task (npair up to 400 -> warps stay fed at all
//   act levels, clamp waste <=1.18x). Inner: 4 LDS.128 w + 4 LDS.128 h ->
//   64 FMA. GX added at the END (LDG hidden under the 50-iter loop).
// ---------------------------------------------------------------------------
#define NCL  33
#define CLW  4
#define RMAX 32
#define RW   4
#define WLT  512
// Wsm [50][201] float4 + h[2][32][200] f + c[32*50] f + len/s ints
#define WL_SMEM (50 * 201 * 16 + 2 * RMAX * 200 * 4 + RMAX * 50 * 4 + RMAX * 8)

__global__ void __cluster_dims__(CLW, 1, 1) __launch_bounds__(WLT, 1)
wordlstm_kernel(const float* __restrict__ h0w, const float* __restrict__ c0w,
                const int* __restrict__ lengths) {
    extern __shared__ float smemf[];
    float4* Wsm   = (float4*)smemf;                    // [50][201] (pad: stride 201)
    float*  hb    = (float*)(Wsm + 50 * 201);          // [2][RMAX*200]
    float*  c_sm  = hb + 2 * RMAX * 200;               // [RMAX*50]
    int*    len_sm = (int*)(c_sm + RMAX * 50);         // [RMAX]
    int*    s_sm   = len_sm + RMAX;                    // [RMAX]

    int tid = threadIdx.x;
    int rk  = blockIdx.x % CLW;    // cta rank in cluster (kappa slice)
    int cid = blockIdx.x / CLW;    // cluster id

    // Stage Whh slice (50 kappa x 200 k, gate-interleaved float4)
    for (int idx = tid; idx < 50 * 200; idx += WLT) {
        int kl = idx / 200, k = idx % 200;
        Wsm[kl * 201 + k] = g_W4[0][(rk * 50 + kl) * K2 + H + k];
    }
    // Init h (buffer 0), c, lengths, sentence ids
    for (int idx = tid; idx < RMAX * 200; idx += WLT) {
        int j = idx / 200, k = idx % 200;
        int r = cid + NCL * j;
        hb[idx] = (r < S) ? h0w[g_order[r] * H + k] : 0.f;
    }
    for (int idx = tid; idx < RMAX * 50; idx += WLT) {
        int j = idx / 50, kl = idx % 50;
        int r = cid + NCL * j;
        c_sm[idx] = (r < S) ? c0w[g_order[r] * H + rk * 50 + kl] : 0.f;
    }
    if (tid < RMAX) {
        int r = cid + NCL * tid;
        int s = (r < S) ? g_order[r] : 0;
        s_sm[tid] = s;
        len_sm[tid] = (r < S) ? lengths[s] : 0;
    }
    __syncthreads();
    cluster_sync_();   // peers' h buffers + weights ready before any step

    int p = 0;
    for (int t = 0; t < W; t++) {
        int cnt = g_cnt[t];
        if (cnt <= cid) break;                       // uniform per cluster
        int act = (cnt - cid + NCL - 1) / NCL;       // active rows (prefix in j)
        const float* __restrict__ hin = hb + p * (RMAX * 200);
        float* hout = hb + (p ^ 1) * (RMAX * 200);
        long gxb = g_off[t];
        int ntask = ((act + RW - 1) / RW) * 50;      // RW rows per weight load

        for (int idx = tid; idx < ntask; idx += WLT) {
            int jp = idx / 50, kl = idx % 50;
            int j0 = RW * jp;
            int kg = rk * 50 + kl;
            int jc[RW];
            float4 gxv[RW];
            float4 acc[RW];
            const float4* hp4[RW];
#pragma unroll
            for (int n = 0; n < RW; n++) {
                jc[n] = (j0 + n < act) ? j0 + n : act - 1;
                gxv[n] = g_GX4[(gxb + cid + (long)NCL * jc[n]) * H + kg];
                hp4[n] = (const float4*)&hin[jc[n] * 200];
                acc[n] = make_float4(0.f, 0.f, 0.f, 0.f);
            }
            const float4* __restrict__ wr = &Wsm[kl * 201];
#pragma unroll 2
            for (int k4 = 0; k4 < 50; k4++) {
                float4 w0 = wr[k4 * 4 + 0];
                float4 w1 = wr[k4 * 4 + 1];
                float4 w2 = wr[k4 * 4 + 2];
                float4 w3 = wr[k4 * 4 + 3];
#pragma unroll
                for (int n = 0; n < RW; n++) {
                    float4 a = hp4[n][k4];
                    acc[n].x = fmaf(w0.x, a.x, acc[n].x);
                    acc[n].y = fmaf(w0.y, a.x, acc[n].y);
                    acc[n].z = fmaf(w0.z, a.x, acc[n].z);
                    acc[n].w = fmaf(w0.w, a.x, acc[n].w);
                    acc[n].x = fmaf(w1.x, a.y, acc[n].x);
                    acc[n].y = fmaf(w1.y, a.y, acc[n].y);
                    acc[n].z = fmaf(w1.z, a.y, acc[n].z);
                    acc[n].w = fmaf(w1.w, a.y, acc[n].w);
                    acc[n].x = fmaf(w2.x, a.z, acc[n].x);
                    acc[n].y = fmaf(w2.y, a.z, acc[n].y);
                    acc[n].z = fmaf(w2.z, a.z, acc[n].z);
                    acc[n].w = fmaf(w2.w, a.z, acc[n].w);
                    acc[n].x = fmaf(w3.x, a.w, acc[n].x);
                    acc[n].y = fmaf(w3.y, a.w, acc[n].y);
                    acc[n].z = fmaf(w3.z, a.w, acc[n].z);
                    acc[n].w = fmaf(w3.w, a.w, acc[n].w);
                }
            }
#pragma unroll
            for (int n = 0; n < RW; n++) {
                int j = j0 + n;
                if (j >= act) break;
                float ig = sigf(acc[n].x + gxv[n].x);
                float fg = sigf(acc[n].y + gxv[n].y);
                float gg = tanhf(acc[n].z + gxv[n].z);
                float og = sigf(acc[n].w + gxv[n].w);
                float c = fg * c_sm[j * 50 + kl] + ig * gg;
                c_sm[j * 50 + kl] = c;
                float h = og * tanhf(c);
                // broadcast h into next-parity buffer of ALL 4 cluster CTAs
                uint32_t laddr = (uint32_t)__cvta_generic_to_shared(
                    &hout[j * 200 + kg]);
#pragma unroll
                for (int tr = 0; tr < CLW; tr++) {
                    uint32_t ra;
                    asm volatile("mapa.shared::cluster.u32 %0, %1, %2;"
                                 : "=r"(ra) : "r"(laddr), "r"(tr));
                    asm volatile("st.shared::cluster.f32 [%0], %1;"
                                 :: "r"(ra), "f"(h) : "memory");
                }
                if (len_sm[j] == t + 1)
                    g_emb[s_sm[j] * H + kg] = h;
            }
        }
        cluster_sync_();   // remote h stores visible before next step reads
        p ^= 1;
    }
}

// ---------------------------------------------------------------------------
// Kernel 5: input projections  out4[t][kap] = b4 + W_in . x(t)
// ---------------------------------------------------------------------------
__global__ void proj_kernel(const float* __restrict__ words, int x_sel, int T, int set) {
    int t = blockIdx.x;
    if (t >= T) return;
    const float* xbase;
    long xstride;
    float4* out;
    if (x_sel == 0)      { xbase = words + (long)MID * W * H; xstride =  H; out = g_GT4; }
    else if (x_sel == 1) { xbase = g_emb;                     xstride =  H; out = g_GP4; }
    else                 { xbase = g_emb + (long)(S - 1) * H; xstride = -H; out = g_GQ4; }

    __shared__ float xs[H];
    int tid = threadIdx.x;
    if (tid < H) xs[tid] = xbase[(long)t * xstride + tid];
    __syncthreads();
    if (tid >= H) return;
    int kap = tid;
    const float4* __restrict__ wr = &g_W4[set][kap * K2];
    float4 acc = g_b4[set][kap];
#pragma unroll 4
    for (int k = 0; k < H; k++) {
        float a = xs[k];
        float4 w = wr[k];
        acc.x = fmaf(w.x, a, acc.x);
        acc.y = fmaf(w.y, a, acc.y);
        acc.z = fmaf(w.z, a, acc.z);
        acc.w = fmaf(w.w, a, acc.w);
    }
    out[t * H + kap] = acc;
}

// ---------------------------------------------------------------------------
// Kernel 6: serial LSTM recurrence, 4-CTA cluster, whh slice in SMEM
// ---------------------------------------------------------------------------
#define CL 4
struct RecParams {
    int gx_sel;
    int set;
    const float* h0;
    const float* c0;
    int out_sel;
    int steps;
    const int* steps_dev;
};

#define REC_SMEM (50 * H * 16 + 256 * 4 + 64 * 4 + 4 * 50 * 16)

__global__ void __cluster_dims__(CL, 1, 1) __launch_bounds__(256, 1)
rec_kernel(RecParams p0, RecParams p1, int ncl) {
    int cid = blockIdx.x / CL;
    if (cid >= ncl) return;
    RecParams P = (cid == 0) ? p0 : p1;

    const float4* gx = (P.gx_sel == 0) ? g_GT4 : (P.gx_sel == 1) ? g_GP4 : g_GQ4;
    float* out = (P.out_sel == 0) ? (g_emb + (long)MID * H)
               : (P.out_sel == 1) ? g_prevh : g_posth;
    const float4* w4 = g_W4[P.set];

    extern __shared__ float smem[];
    float4* Wsm = (float4*)smem;                       // [50][200]
    float*  h_sm = (float*)(Wsm + 50 * H);             // [200] (pad 256)
    float*  c_sm = h_sm + 256;                         // [50]  (pad 64)
    float4* psum = (float4*)(c_sm + 64);               // [4][50]

    int tid = threadIdx.x;
    int r = blockIdx.x % CL;

    for (int idx = tid; idx < 50 * H; idx += 256) {
        int kl = idx / H, k = idx % H;
        Wsm[kl * H + k] = w4[(r * 50 + kl) * K2 + H + k];
    }
    for (int k = tid; k < H; k += 256) h_sm[k] = P.h0[k];
    if (tid < 50) c_sm[tid] = P.c0[r * 50 + tid];
    int steps = P.steps_dev ? P.steps_dev[0] : P.steps;
    __syncthreads();
    cluster_sync_();

    for (int t = 0; t < steps; t++) {
        if (tid < 200) {
            int c4 = tid & 3, kl = tid >> 2;
            float4 acc = make_float4(0.f, 0.f, 0.f, 0.f);
            const float4* wrow = &Wsm[kl * H + c4 * 50];
            const float* hp = &h_sm[c4 * 50];
#pragma unroll 10
            for (int k = 0; k < 50; k++) {
                float a = hp[k];
                float4 w = wrow[k];
                acc.x = fmaf(w.x, a, acc.x);
                acc.y = fmaf(w.y, a, acc.y);
                acc.z = fmaf(w.z, a, acc.z);
                acc.w = fmaf(w.w, a, acc.w);
            }
            psum[c4 * 50 + kl] = acc;
        }
        __syncthreads();
        if (tid < 50) {
            float4 g = gx[t * H + r * 50 + tid];
            float4 a0 = psum[0 * 50 + tid], a1 = psum[1 * 50 + tid];
            float4 a2 = psum[2 * 50 + tid], a3 = psum[3 * 50 + tid];
            g.x += a0.x + a1.x + a2.x + a3.x;
            g.y += a0.y + a1.y + a2.y + a3.y;
            g.z += a0.z + a1.z + a2.z + a3.z;
            g.w += a0.w + a1.w + a2.w + a3.w;
            float ig = sigf(g.x), fg = sigf(g.y), gg = tanhf(g.z), og = sigf(g.w);
            float cn = fg * c_sm[tid] + ig * gg;
            c_sm[tid] = cn;
            float hn = og * tanhf(cn);
            int hidx = r * 50 + tid;
            uint32_t laddr = (uint32_t)__cvta_generic_to_shared(&h_sm[hidx]);
#pragma unroll
            for (int tr = 0; tr < CL; tr++) {
                uint32_t raddr;
                asm volatile("mapa.shared::cluster.u32 %0, %1, %2;"
                             : "=r"(raddr) : "r"(laddr), "r"(tr));
                asm volatile("st.shared::cluster.f32 [%0], %1;"
                             :: "r"(raddr), "f"(hn) : "memory");
            }
        }
        cluster_sync_();
    }

    if (tid < 50) out[r * 50 + tid] = h_sm[r * 50 + tid];
}

// ---------------------------------------------------------------------------
// Kernel 7: final FC
// ---------------------------------------------------------------------------
__global__ void fc_kernel(const float* __restrict__ fcw,
                          const float* __restrict__ fcb,
                          float* __restrict__ out) {
    __shared__ float feat[K2];
    int tid = threadIdx.x;
    if (tid < H) { feat[tid] = g_prevh[tid]; feat[H + tid] = g_posth[tid]; }
    __syncthreads();
    if (tid < H) {
        float acc = fcb[tid];
        const float* wr = &fcw[tid * K2];
#pragma unroll 4
        for (int k = 0; k < K2; k++) acc = fmaf(wr[k], feat[k], acc);
        out[tid] = acc;
    }
}

// ---------------------------------------------------------------------------
// Launch
// ---------------------------------------------------------------------------
extern "C" void kernel_launch(void* const* d_in, const int* in_sizes, int n_in,
                              void* d_out, int out_size) {
    const float* words   = (const float*)d_in[0];
    const int*   lengths = (const int*)  d_in[1];
    const float* h0w     = (const float*)d_in[2];
    const float* c0w     = (const float*)d_in[3];
    const float* h0p     = (const float*)d_in[4];
    const float* c0p     = (const float*)d_in[5];
    const float* h0q     = (const float*)d_in[6];
    const float* c0q     = (const float*)d_in[7];
    const float* fc_w    = (const float*)d_in[24];
    const float* fc_b    = (const float*)d_in[25];
    float* out = (float*)d_out;

    cudaFuncSetAttribute(rec_kernel, cudaFuncAttributeMaxDynamicSharedMemorySize,
                         REC_SMEM);
    cudaFuncSetAttribute(wordlstm_kernel,
                         cudaFuncAttributeMaxDynamicSharedMemorySize, WL_SMEM);

    // 1. sort sentences by length (desc) + counts + prefix offsets
    sort_kernel<<<1, 256>>>(lengths);

    // 2. all weight reorders in ONE launch
    PrepArgs pa;
    for (int i = 0; i < 4; i++) {
        pa.wih[i] = (const float*)d_in[8 + 4 * i];
        pa.whh[i] = (const float*)d_in[9 + 4 * i];
        pa.bih[i] = (const float*)d_in[10 + 4 * i];
        pa.bhh[i] = (const float*)d_in[11 + 4 * i];
    }
    dim3 pgrid((H * K2 + 255) / 256, 4);
    prep_kernel<<<pgrid, 256>>>(pa);

    // 3. GX: fully-parallel ragged input-projection GEMM (32-row tiles)
    dim3 ggrid(NKT, (S + GMT - 1) / GMT, W);
    gx_kernel<<<ggrid, 256>>>(words);

    // 4. WORD LSTM: one launch, 33 independent 4-CTA clusters, Whh in SMEM
    wordlstm_kernel<<<NCL * CLW, WLT, WL_SMEM>>>(h0w, c0w, lengths);

    // 5. tgt input projection + recurrence overwrites emb[MID]
    proj_kernel<<<W, 256>>>(words, 0, W, 1);
    RecParams Ptgt;
    Ptgt.gx_sel = 0; Ptgt.set = 1;
    Ptgt.h0 = h0w + (long)MID * H; Ptgt.c0 = c0w + (long)MID * H;
    Ptgt.out_sel = 0; Ptgt.steps = 0; Ptgt.steps_dev = lengths + MID;
    rec_kernel<<<CL, 256, REC_SMEM>>>(Ptgt, Ptgt, 1);

    // 6. prev/post input projections
    proj_kernel<<<NSEQ_PREV, 256>>>(words, 1, NSEQ_PREV, 2);
    proj_kernel<<<NSEQ_PREV, 256>>>(words, 2, NSEQ_PREV, 3);

    // 7. prev + post recurrences, concurrent
    RecParams Pprev, Ppost;
    Pprev.gx_sel = 1; Pprev.set = 2; Pprev.h0 = h0p; Pprev.c0 = c0p;
    Pprev.out_sel = 1; Pprev.steps = NSEQ_PREV; Pprev.steps_dev = nullptr;
    Ppost.gx_sel = 2; Ppost.set = 3; Ppost.h0 = h0q; Ppost.c0 = c0q;
    Ppost.out_sel = 2; Ppost.steps = NSEQ_PREV; Ppost.steps_dev = nullptr;
    rec_kernel<<<2 * CL, 256, REC_SMEM>>>(Pprev, Ppost, 2);

    // 8. final FC -> d_out [200]
    fc_kernel<<<1, 256>>>(fc_w, fc_b, out);
}